// round 3
// baseline (speedup 1.0000x reference)
#include <cuda_runtime.h>

#define Bn   8
#define Sn   4096
#define Dm   512
#define Fn   2049
#define Em   8
#define DFF  2048
#define NT   (Bn * Fn)      /* 16392 tokens in frequency domain */
#define NSLOT (2 * NT)      /* 32784 token-expert slots */

/* ---------------- scratch (device globals; no runtime alloc allowed) -------- */
__device__ float g_xfri[16785408];   /* NT x 1024  (re | im) */
__device__ float g_h   [8392704];    /* NT x 512 */
__device__ float g_moe [8392704];    /* NT x 512 */
__device__ float g_of  [16785408];   /* NT x 1024 */
__device__ float g_ot  [16777216];   /* B x S x D */
__device__ float g_hid [67141632];   /* NSLOT x 2048 */
__device__ float g_eout[16785408];   /* NSLOT x 512 */
__device__ int   g_top_idx[NT * 2];
__device__ float g_top_w [NT * 2];
__device__ int   g_counts[Em];
__device__ int   g_offsets[Em];
__device__ int   g_cursor[Em];
__device__ int   g_slot_token[NSLOT];
__device__ int   g_tok_slot[NT * 2];

/* ---------------- small setup kernels ---------------- */
__global__ void init_kernel() {
    int i = threadIdx.x;
    if (i < Em) g_counts[i] = 0;
}

/* ---------------- forward rfft: one block per (b, d) column ---------------- */
__global__ void fft_fwd_kernel(const float* __restrict__ x) {
    __shared__ float re[4096];
    __shared__ float im[4096];
    int col = blockIdx.x;
    int b = col >> 9, d = col & 511;
    int tid = threadIdx.x;

    for (int s = tid; s < 4096; s += 256) {
        int r = (int)(__brev((unsigned)s) >> 20);
        re[r] = x[((size_t)b * Sn + s) * Dm + d];
        im[r] = 0.f;
    }
    __syncthreads();

    for (int st = 1; st <= 12; ++st) {
        int half = 1 << (st - 1);
        for (int j = tid; j < 2048; j += 256) {
            int pos = j & (half - 1);
            int i0  = ((j >> (st - 1)) << st) + pos;
            int i1  = i0 + half;
            float ang = -6.283185307179586f * (float)pos / (float)(1 << st);
            float sn, cs;
            sincosf(ang, &sn, &cs);
            float ur = re[i0], ui = im[i0];
            float vr = re[i1], vi = im[i1];
            float tr = vr * cs - vi * sn;
            float ti = vr * sn + vi * cs;
            re[i0] = ur + tr; im[i0] = ui + ti;
            re[i1] = ur - tr; im[i1] = ui - ti;
        }
        __syncthreads();
    }

    const float sc = 0.015625f;   /* 1/sqrt(4096) */
    for (int k = tid; k < Fn; k += 256) {
        size_t o = ((size_t)b * Fn + k) * 1024 + d;
        g_xfri[o]       = re[k] * sc;
        g_xfri[o + 512] = im[k] * sc;
    }
}

/* ---------------- inverse rfft ---------------- */
__global__ void fft_inv_kernel() {
    __shared__ float re[4096];
    __shared__ float im[4096];
    int col = blockIdx.x;
    int b = col >> 9, d = col & 511;
    int tid = threadIdx.x;

    for (int s = tid; s < 4096; s += 256) {
        float yr, yi;
        if (s <= 2048) {
            size_t o = ((size_t)b * Fn + s) * 1024 + d;
            yr = g_of[o];
            yi = g_of[o + 512];
        } else {
            int k2 = 4096 - s;
            size_t o = ((size_t)b * Fn + k2) * 1024 + d;
            yr =  g_of[o];
            yi = -g_of[o + 512];
        }
        int r = (int)(__brev((unsigned)s) >> 20);
        re[r] = yr;
        im[r] = yi;
    }
    __syncthreads();

    for (int st = 1; st <= 12; ++st) {
        int half = 1 << (st - 1);
        for (int j = tid; j < 2048; j += 256) {
            int pos = j & (half - 1);
            int i0  = ((j >> (st - 1)) << st) + pos;
            int i1  = i0 + half;
            float ang = 6.283185307179586f * (float)pos / (float)(1 << st);
            float sn, cs;
            sincosf(ang, &sn, &cs);
            float ur = re[i0], ui = im[i0];
            float vr = re[i1], vi = im[i1];
            float tr = vr * cs - vi * sn;
            float ti = vr * sn + vi * cs;
            re[i0] = ur + tr; im[i0] = ui + ti;
            re[i1] = ur - tr; im[i1] = ui - ti;
        }
        __syncthreads();
    }

    const float sc = 0.015625f;
    for (int s = tid; s < 4096; s += 256)
        g_ot[((size_t)b * Sn + s) * Dm + d] = re[s] * sc;
}

/* ---------------- dense GEMM: 64x64x16 tile, 4x4 microtile ----------------
   MODE 0: g_h  = g_xfri @ pin_w + pin_b   (K=1024, N=512)
   MODE 1: g_of = g_moe  @ pout_w + pout_b (K=512,  N=1024)                 */
template <int MODE>
__global__ void gemm_dense_kernel(const float* __restrict__ W,
                                  const float* __restrict__ bias) {
    constexpr int K = (MODE == 0) ? 1024 : 512;
    constexpr int N = (MODE == 0) ? 512 : 1024;
    const float* A = (MODE == 0) ? g_xfri : g_moe;
    float*       C = (MODE == 0) ? g_h : g_of;
    const int M = NT;

    __shared__ __align__(16) float As[16][64];
    __shared__ __align__(16) float Bs[16][64];

    int tid = threadIdx.x;
    int tx = tid & 15, ty = tid >> 4;
    int m0 = blockIdx.y * 64, n0 = blockIdx.x * 64;
    int arow = tid >> 2, acol = (tid & 3) << 2;
    int brow = tid >> 4, bcol = (tid & 15) << 2;

    float c[4][4];
#pragma unroll
    for (int i = 0; i < 4; i++)
#pragma unroll
        for (int j = 0; j < 4; j++) c[i][j] = 0.f;

    int gm = m0 + arow;
    const float* Arow = (gm < M) ? (A + (size_t)gm * K) : nullptr;

    for (int k0 = 0; k0 < K; k0 += 16) {
        float4 av = make_float4(0.f, 0.f, 0.f, 0.f);
        if (Arow) av = *(const float4*)(Arow + k0 + acol);
        As[acol + 0][arow] = av.x;
        As[acol + 1][arow] = av.y;
        As[acol + 2][arow] = av.z;
        As[acol + 3][arow] = av.w;
        *(float4*)&Bs[brow][bcol] =
            *(const float4*)(W + (size_t)(k0 + brow) * N + n0 + bcol);
        __syncthreads();
#pragma unroll
        for (int kk = 0; kk < 16; ++kk) {
            float4 a  = *(const float4*)&As[kk][ty << 2];
            float4 bq = *(const float4*)&Bs[kk][tx << 2];
            float aa[4] = {a.x, a.y, a.z, a.w};
            float bb[4] = {bq.x, bq.y, bq.z, bq.w};
#pragma unroll
            for (int i = 0; i < 4; i++)
#pragma unroll
                for (int j = 0; j < 4; j++) c[i][j] += aa[i] * bb[j];
        }
        __syncthreads();
    }

#pragma unroll
    for (int i = 0; i < 4; i++) {
        int m = m0 + (ty << 2) + i;
        if (m < M) {
#pragma unroll
            for (int j = 0; j < 4; j++) {
                int n = n0 + (tx << 2) + j;
                C[(size_t)m * N + n] = c[i][j] + bias[n];
            }
        }
    }
}

/* ---------------- router: one warp per token ---------------- */
__global__ void router_kernel(const float* __restrict__ rw,
                              const float* __restrict__ rb) {
    int t = blockIdx.x;
    int lane = threadIdx.x;
    const float* h = g_h + (size_t)t * Dm;
    float acc[Em];
#pragma unroll
    for (int e = 0; e < Em; e++) acc[e] = 0.f;

    for (int k = lane; k < Dm; k += 32) {
        float hv = h[k];
        const float* r = rw + k * Em;
#pragma unroll
        for (int e = 0; e < Em; e++) acc[e] += hv * r[e];
    }
#pragma unroll
    for (int e = 0; e < Em; e++)
        for (int o = 16; o; o >>= 1)
            acc[e] += __shfl_down_sync(0xffffffffu, acc[e], o);

    if (lane == 0) {
        float best = -1e30f, second = -1e30f;
        int bi = 0, si = 0;
#pragma unroll
        for (int e = 0; e < Em; e++) {
            float l = acc[e] + rb[e];
            if (l > best)       { second = best; si = bi; best = l; bi = e; }
            else if (l > second){ second = l; si = e; }
        }
        float e1 = expf(second - best);
        float inv = 1.f / (1.f + e1);
        g_top_idx[2 * t]     = bi;
        g_top_idx[2 * t + 1] = si;
        g_top_w[2 * t]       = inv;
        g_top_w[2 * t + 1]   = e1 * inv;
    }
}

__global__ void hist_kernel() {
    int t = blockIdx.x * blockDim.x + threadIdx.x;
    if (t < NT) {
        atomicAdd(&g_counts[g_top_idx[2 * t]], 1);
        atomicAdd(&g_counts[g_top_idx[2 * t + 1]], 1);
    }
}

__global__ void scan_kernel() {
    if (threadIdx.x == 0) {
        int off = 0;
        for (int e = 0; e < Em; e++) {
            g_offsets[e] = off;
            g_cursor[e]  = off;
            off += g_counts[e];
        }
    }
}

__global__ void scatter_kernel() {
    int t = blockIdx.x * blockDim.x + threadIdx.x;
    if (t < NT) {
        for (int k = 0; k < 2; k++) {
            int e = g_top_idx[2 * t + k];
            int slot = atomicAdd(&g_cursor[e], 1);
            g_slot_token[slot] = t;
            g_tok_slot[2 * t + k] = slot;
        }
    }
}

/* ---------------- MoE GEMM 1: hid = gelu(h @ w1[e] + b1[e]) --------------- */
__global__ void moe_gemm1_kernel(const float* __restrict__ w1,
                                 const float* __restrict__ b1) {
    int e = blockIdx.z;
    int cnt = g_counts[e];
    int m0 = blockIdx.y * 64;
    if (m0 >= cnt) return;
    int base = g_offsets[e];
    const float* W = w1 + (size_t)e * Dm * DFF;
    constexpr int K = Dm, N = DFF;

    __shared__ __align__(16) float As[16][64];
    __shared__ __align__(16) float Bs[16][64];

    int tid = threadIdx.x;
    int tx = tid & 15, ty = tid >> 4;
    int n0 = blockIdx.x * 64;
    int arow = tid >> 2, acol = (tid & 3) << 2;
    int brow = tid >> 4, bcol = (tid & 15) << 2;

    float c[4][4];
#pragma unroll
    for (int i = 0; i < 4; i++)
#pragma unroll
        for (int j = 0; j < 4; j++) c[i][j] = 0.f;

    int gm = m0 + arow;
    const float* Arow = nullptr;
    if (gm < cnt) Arow = g_h + (size_t)g_slot_token[base + gm] * Dm;

    for (int k0 = 0; k0 < K; k0 += 16) {
        float4 av = make_float4(0.f, 0.f, 0.f, 0.f);
        if (Arow) av = *(const float4*)(Arow + k0 + acol);
        As[acol + 0][arow] = av.x;
        As[acol + 1][arow] = av.y;
        As[acol + 2][arow] = av.z;
        As[acol + 3][arow] = av.w;
        *(float4*)&Bs[brow][bcol] =
            *(const float4*)(W + (size_t)(k0 + brow) * N + n0 + bcol);
        __syncthreads();
#pragma unroll
        for (int kk = 0; kk < 16; ++kk) {
            float4 a  = *(const float4*)&As[kk][ty << 2];
            float4 bq = *(const float4*)&Bs[kk][tx << 2];
            float aa[4] = {a.x, a.y, a.z, a.w};
            float bb[4] = {bq.x, bq.y, bq.z, bq.w};
#pragma unroll
            for (int i = 0; i < 4; i++)
#pragma unroll
                for (int j = 0; j < 4; j++) c[i][j] += aa[i] * bb[j];
        }
        __syncthreads();
    }

#pragma unroll
    for (int i = 0; i < 4; i++) {
        int m = m0 + (ty << 2) + i;
        if (m < cnt) {
#pragma unroll
            for (int j = 0; j < 4; j++) {
                int n = n0 + (tx << 2) + j;
                float v = c[i][j] + b1[e * DFF + n];
                float g = 0.5f * v * (1.f + erff(v * 0.7071067811865475f));
                g_hid[(size_t)(base + m) * DFF + n] = g;
            }
        }
    }
}

/* ---------------- MoE GEMM 2: eout = hid @ w2[e] + b2[e] ---------------- */
__global__ void moe_gemm2_kernel(const float* __restrict__ w2,
                                 const float* __restrict__ b2) {
    int e = blockIdx.z;
    int cnt = g_counts[e];
    int m0 = blockIdx.y * 64;
    if (m0 >= cnt) return;
    int base = g_offsets[e];
    const float* W = w2 + (size_t)e * DFF * Dm;
    constexpr int K = DFF, N = Dm;

    __shared__ __align__(16) float As[16][64];
    __shared__ __align__(16) float Bs[16][64];

    int tid = threadIdx.x;
    int tx = tid & 15, ty = tid >> 4;
    int n0 = blockIdx.x * 64;
    int arow = tid >> 2, acol = (tid & 3) << 2;
    int brow = tid >> 4, bcol = (tid & 15) << 2;

    float c[4][4];
#pragma unroll
    for (int i = 0; i < 4; i++)
#pragma unroll
        for (int j = 0; j < 4; j++) c[i][j] = 0.f;

    int gm = m0 + arow;
    const float* Arow = (gm < cnt) ? (g_hid + (size_t)(base + gm) * K) : nullptr;

    for (int k0 = 0; k0 < K; k0 += 16) {
        float4 av = make_float4(0.f, 0.f, 0.f, 0.f);
        if (Arow) av = *(const float4*)(Arow + k0 + acol);
        As[acol + 0][arow] = av.x;
        As[acol + 1][arow] = av.y;
        As[acol + 2][arow] = av.z;
        As[acol + 3][arow] = av.w;
        *(float4*)&Bs[brow][bcol] =
            *(const float4*)(W + (size_t)(k0 + brow) * N + n0 + bcol);
        __syncthreads();
#pragma unroll
        for (int kk = 0; kk < 16; ++kk) {
            float4 a  = *(const float4*)&As[kk][ty << 2];
            float4 bq = *(const float4*)&Bs[kk][tx << 2];
            float aa[4] = {a.x, a.y, a.z, a.w};
            float bb[4] = {bq.x, bq.y, bq.z, bq.w};
#pragma unroll
            for (int i = 0; i < 4; i++)
#pragma unroll
                for (int j = 0; j < 4; j++) c[i][j] += aa[i] * bb[j];
        }
        __syncthreads();
    }

#pragma unroll
    for (int i = 0; i < 4; i++) {
        int m = m0 + (ty << 2) + i;
        if (m < cnt) {
#pragma unroll
            for (int j = 0; j < 4; j++) {
                int n = n0 + (tx << 2) + j;
                g_eout[(size_t)(base + m) * Dm + n] = c[i][j] + b2[e * Dm + n];
            }
        }
    }
}

/* ---------------- combine top-2 expert outputs (deterministic) ------------ */
__global__ void combine_kernel() {
    int i = blockIdx.x * blockDim.x + threadIdx.x;
    if (i >= NT * Dm) return;
    int t = i >> 9, d = i & 511;
    int s0 = g_tok_slot[2 * t], s1 = g_tok_slot[2 * t + 1];
    g_moe[i] = g_top_w[2 * t]     * g_eout[(size_t)s0 * Dm + d]
             + g_top_w[2 * t + 1] * g_eout[(size_t)s1 * Dm + d];
}

/* ---------------- LayerNorm + residual ---------------- */
__global__ void ln_kernel(const float* __restrict__ x,
                          const float* __restrict__ gg,
                          const float* __restrict__ bb,
                          float* __restrict__ out) {
    int row = blockIdx.x;              /* 0 .. B*S-1 */
    int tid = threadIdx.x;             /* 128 threads */
    const float* v = g_ot + (size_t)row * Dm;

    float loc[4];
    float s = 0.f;
#pragma unroll
    for (int i = 0; i < 4; i++) {
        loc[i] = v[tid + i * 128];
        s += loc[i];
    }

    __shared__ float red[4];
    for (int o = 16; o; o >>= 1) s += __shfl_down_sync(0xffffffffu, s, o);
    if ((tid & 31) == 0) red[tid >> 5] = s;
    __syncthreads();
    float mu = (red[0] + red[1] + red[2] + red[3]) * (1.f / 512.f);
    __syncthreads();

    float q = 0.f;
#pragma unroll
    for (int i = 0; i < 4; i++) {
        float dd = loc[i] - mu;
        q += dd * dd;
    }
    for (int o = 16; o; o >>= 1) q += __shfl_down_sync(0xffffffffu, q, o);
    if ((tid & 31) == 0) red[tid >> 5] = q;
    __syncthreads();
    float var = (red[0] + red[1] + red[2] + red[3]) * (1.f / 512.f);
    float rs = rsqrtf(var + 1e-5f);

#pragma unroll
    for (int i = 0; i < 4; i++) {
        int d = tid + i * 128;
        size_t o = (size_t)row * Dm + d;
        out[o] = (loc[i] - mu) * rs * gg[d] + bb[d] + x[o];
    }
}

/* ---------------- launch ---------------- */
extern "C" void kernel_launch(void* const* d_in, const int* in_sizes, int n_in,
                              void* d_out, int out_size) {
    const float* x        = (const float*)d_in[0];
    const float* pin_w    = (const float*)d_in[1];
    const float* pin_b    = (const float*)d_in[2];
    const float* router_w = (const float*)d_in[3];
    const float* router_b = (const float*)d_in[4];
    const float* w1       = (const float*)d_in[5];
    const float* b1       = (const float*)d_in[6];
    const float* w2       = (const float*)d_in[7];
    const float* b2       = (const float*)d_in[8];
    const float* pout_w   = (const float*)d_in[9];
    const float* pout_b   = (const float*)d_in[10];
    const float* ln_g     = (const float*)d_in[11];
    const float* ln_b     = (const float*)d_in[12];
    float* out = (float*)d_out;

    init_kernel<<<1, 32>>>();
    fft_fwd_kernel<<<Bn * Dm, 256>>>(x);
    gemm_dense_kernel<0><<<dim3(512 / 64, (NT + 63) / 64), 256>>>(pin_w, pin_b);
    router_kernel<<<NT, 32>>>(router_w, router_b);
    hist_kernel<<<(NT + 255) / 256, 256>>>();
    scan_kernel<<<1, 1>>>();
    scatter_kernel<<<(NT + 255) / 256, 256>>>();
    moe_gemm1_kernel<<<dim3(DFF / 64, (NT + 63) / 64, Em), 256>>>(w1, b1);
    moe_gemm2_kernel<<<dim3(Dm / 64, (NT + 63) / 64, Em), 256>>>(w2, b2);
    combine_kernel<<<(NT * Dm + 255) / 256, 256>>>();
    gemm_dense_kernel<1><<<dim3(1024 / 64, (NT + 63) / 64), 256>>>(pout_w, pout_b);
    fft_inv_kernel<<<Bn * Dm, 256>>>();
    ln_kernel<<<Bn * Sn, 128>>>(x, ln_g, ln_b, out);
}

// round 5
// speedup vs baseline: 1.8645x; 1.8645x over previous
#include <cuda_runtime.h>

#define Bn   8
#define Sn   4096
#define Dm   512
#define Fn   2049
#define Em   8
#define DFF  2048
#define NT   (Bn * Fn)      /* 16392 tokens in frequency domain */
#define NSLOT (2 * NT)      /* 32784 token-expert slots */

/* ---------------- scratch (device globals; no runtime alloc allowed) -------- */
__device__ float g_xfri[16785408];   /* NT x 1024  (re | im) */
__device__ float g_h   [8392704];    /* NT x 512 */
__device__ float g_moe [8392704];    /* NT x 512 */
__device__ float g_of  [16785408];   /* NT x 1024 */
__device__ float g_ot  [16777216];   /* B x S x D */
__device__ float g_hid [67141632];   /* NSLOT x 2048 */
__device__ float g_eout[16785408];   /* NSLOT x 512 */
__device__ float2 g_tw [4096];       /* twiddle table: index = half + pos */
__device__ int   g_top_idx[NT * 2];
__device__ float g_top_w [NT * 2];
__device__ int   g_counts[Em];
__device__ int   g_offsets[Em];
__device__ int   g_cursor[Em];
__device__ int   g_slot_token[NSLOT];
__device__ int   g_tok_slot[NT * 2];

/* ---------------- setup: zero counts + build twiddle table ---------------- */
__global__ void setup_kernel() {
    int i = blockIdx.x * blockDim.x + threadIdx.x;
    if (i < Em) g_counts[i] = 0;
    if (i >= 1 && i < 4096) {
        int half = 1 << (31 - __clz(i));
        int pos  = i - half;
        float ang = -6.283185307179586f * (float)pos / (float)(2 * half);
        float sn, cs;
        sincosf(ang, &sn, &cs);
        g_tw[i] = make_float2(cs, sn);
    }
}

/* ---------------- forward rfft: one block per (b, d) column ---------------- */
__global__ void fft_fwd_kernel(const float* __restrict__ x) {
    __shared__ float re[4096];
    __shared__ float im[4096];
    int col = blockIdx.x;
    int b = col >> 9, d = col & 511;
    int tid = threadIdx.x;

    for (int s = tid; s < 4096; s += 256) {
        int r = (int)(__brev((unsigned)s) >> 20);
        re[r] = x[((size_t)b * Sn + s) * Dm + d];
        im[r] = 0.f;
    }
    __syncthreads();

    for (int st = 1; st <= 12; ++st) {
        int half = 1 << (st - 1);
        for (int j = tid; j < 2048; j += 256) {
            int pos = j & (half - 1);
            int i0  = ((j >> (st - 1)) << st) + pos;
            int i1  = i0 + half;
            float2 w = g_tw[half + pos];
            float cs = w.x, sn = w.y;
            float ur = re[i0], ui = im[i0];
            float vr = re[i1], vi = im[i1];
            float tr = vr * cs - vi * sn;
            float ti = vr * sn + vi * cs;
            re[i0] = ur + tr; im[i0] = ui + ti;
            re[i1] = ur - tr; im[i1] = ui - ti;
        }
        __syncthreads();
    }

    const float sc = 0.015625f;   /* 1/sqrt(4096) */
    for (int k = tid; k < Fn; k += 256) {
        size_t o = ((size_t)b * Fn + k) * 1024 + d;
        g_xfri[o]       = re[k] * sc;
        g_xfri[o + 512] = im[k] * sc;
    }
}

/* ---------------- inverse rfft ---------------- */
__global__ void fft_inv_kernel() {
    __shared__ float re[4096];
    __shared__ float im[4096];
    int col = blockIdx.x;
    int b = col >> 9, d = col & 511;
    int tid = threadIdx.x;

    for (int s = tid; s < 4096; s += 256) {
        float yr, yi;
        if (s <= 2048) {
            size_t o = ((size_t)b * Fn + s) * 1024 + d;
            yr = g_of[o];
            yi = g_of[o + 512];
        } else {
            int k2 = 4096 - s;
            size_t o = ((size_t)b * Fn + k2) * 1024 + d;
            yr =  g_of[o];
            yi = -g_of[o + 512];
        }
        int r = (int)(__brev((unsigned)s) >> 20);
        re[r] = yr;
        im[r] = yi;
    }
    __syncthreads();

    for (int st = 1; st <= 12; ++st) {
        int half = 1 << (st - 1);
        for (int j = tid; j < 2048; j += 256) {
            int pos = j & (half - 1);
            int i0  = ((j >> (st - 1)) << st) + pos;
            int i1  = i0 + half;
            float2 w = g_tw[half + pos];
            float cs = w.x, sn = -w.y;   /* conjugate for inverse */
            float ur = re[i0], ui = im[i0];
            float vr = re[i1], vi = im[i1];
            float tr = vr * cs - vi * sn;
            float ti = vr * sn + vi * cs;
            re[i0] = ur + tr; im[i0] = ui + ti;
            re[i1] = ur - tr; im[i1] = ui - ti;
        }
        __syncthreads();
    }

    const float sc = 0.015625f;
    for (int s = tid; s < 4096; s += 256)
        g_ot[((size_t)b * Sn + s) * Dm + d] = re[s] * sc;
}

/* ---------------- exact fp32 GEMM for pin (routing must be bit-faithful) ----
   g_h = g_xfri @ pin_w + pin_b   (M=NT, K=1024, N=512), 64x64x16 tile       */
__global__ __launch_bounds__(256) void gemm_pin_fp32_kernel(
        const float* __restrict__ W, const float* __restrict__ bias) {
    constexpr int K = 1024, N = 512;
    const int M = NT;

    __shared__ __align__(16) float As[16][64];
    __shared__ __align__(16) float Bs[16][64];

    int tid = threadIdx.x;
    int tx = tid & 15, ty = tid >> 4;
    int m0 = blockIdx.y * 64, n0 = blockIdx.x * 64;
    int arow = tid >> 2, acol = (tid & 3) << 2;
    int brow = tid >> 4, bcol = (tid & 15) << 2;

    float c[4][4];
#pragma unroll
    for (int i = 0; i < 4; i++)
#pragma unroll
        for (int j = 0; j < 4; j++) c[i][j] = 0.f;

    int gm = m0 + arow;
    const float* Arow = (gm < M) ? (g_xfri + (size_t)gm * K) : nullptr;

    for (int k0 = 0; k0 < K; k0 += 16) {
        float4 av = make_float4(0.f, 0.f, 0.f, 0.f);
        if (Arow) av = *(const float4*)(Arow + k0 + acol);
        As[acol + 0][arow] = av.x;
        As[acol + 1][arow] = av.y;
        As[acol + 2][arow] = av.z;
        As[acol + 3][arow] = av.w;
        *(float4*)&Bs[brow][bcol] =
            *(const float4*)(W + (size_t)(k0 + brow) * N + n0 + bcol);
        __syncthreads();
#pragma unroll
        for (int kk = 0; kk < 16; ++kk) {
            float4 a  = *(const float4*)&As[kk][ty << 2];
            float4 bq = *(const float4*)&Bs[kk][tx << 2];
            float aa[4] = {a.x, a.y, a.z, a.w};
            float bb[4] = {bq.x, bq.y, bq.z, bq.w};
#pragma unroll
            for (int i = 0; i < 4; i++)
#pragma unroll
                for (int j = 0; j < 4; j++) c[i][j] += aa[i] * bb[j];
        }
        __syncthreads();
    }

#pragma unroll
    for (int i = 0; i < 4; i++) {
        int m = m0 + (ty << 2) + i;
        if (m < M) {
#pragma unroll
            for (int j = 0; j < 4; j++) {
                int n = n0 + (tx << 2) + j;
                g_h[(size_t)m * N + n] = c[i][j] + bias[n];
            }
        }
    }
}

/* ==================== tf32 tensor-core GEMM (post-routing only) =========
   Block tile 128(M) x 64(N) x 32(K). 256 threads = 8 warps (4x2).
   Each warp: 32x32 = 2x4 grid of mma.sync.m16n8k8 tf32 tiles.
   MODE 1: g_of  = g_moe  @ pout_w + pout_b              (K=512,  N=1024)
   MODE 2: g_hid = gelu(gather(g_h) @ w1[e] + b1[e])     (K=512,  N=2048)
   MODE 3: g_eout= g_hid @ w2[e] + b2[e]                 (K=2048, N=512)  */

__device__ __forceinline__ unsigned f2tf(float f) {
    unsigned u;
    asm("cvt.rna.tf32.f32 %0, %1;" : "=r"(u) : "f"(f));
    return u;
}

__device__ __forceinline__ void mma_tf32(float c[4], const unsigned a[4],
                                         const unsigned b[2]) {
    asm volatile(
        "mma.sync.aligned.m16n8k8.row.col.f32.tf32.tf32.f32 "
        "{%0,%1,%2,%3}, {%4,%5,%6,%7}, {%8,%9}, {%0,%1,%2,%3};\n"
        : "+f"(c[0]), "+f"(c[1]), "+f"(c[2]), "+f"(c[3])
        : "r"(a[0]), "r"(a[1]), "r"(a[2]), "r"(a[3]), "r"(b[0]), "r"(b[1]));
}

template <int MODE>
__global__ __launch_bounds__(256) void gemm_tf32_kernel(
        const float* __restrict__ W, const float* __restrict__ bias) {
    constexpr int K = (MODE == 1) ? 512 : (MODE == 2) ? 512 : 2048;
    constexpr int N = (MODE == 1) ? 1024 : (MODE == 2) ? 2048 : 512;

    int e = 0, cnt = NT, base = 0;
    if (MODE >= 2) {
        e = blockIdx.z;
        cnt = g_counts[e];
        base = g_offsets[e];
    }
    int m0 = blockIdx.y * 128;
    if (m0 >= cnt) return;
    int n0 = blockIdx.x * 64;

    const float* Wp = W + (MODE >= 2 ? (size_t)e * K * N : 0);
    const float* bp = bias + (MODE >= 2 ? (size_t)e * N : 0);

    __shared__ float As[128][36];
    __shared__ float Bs[32][68];

    int tid = threadIdx.x;
    int wid = tid >> 5, lane = tid & 31;
    int wm = wid >> 1, wn = wid & 1;
    int g = lane >> 2, tq = lane & 3;

    /* hoisted A row pointers for this thread's 4 load rows */
    const float* arow[4];
#pragma unroll
    for (int i = 0; i < 4; i++) {
        int idx = tid + i * 256;
        int r = idx >> 3;
        int m = m0 + r;
        if (m < cnt) {
            if (MODE == 1)      arow[i] = g_moe + (size_t)m * K;
            else if (MODE == 2) arow[i] = g_h + (size_t)g_slot_token[base + m] * K;
            else                arow[i] = g_hid + (size_t)(base + m) * K;
        } else arow[i] = nullptr;
    }

    float acc[2][4][4];
#pragma unroll
    for (int i = 0; i < 2; i++)
#pragma unroll
        for (int j = 0; j < 4; j++)
#pragma unroll
            for (int r = 0; r < 4; r++) acc[i][j][r] = 0.f;

    for (int k0 = 0; k0 < K; k0 += 32) {
        /* load A tile 128x32 */
#pragma unroll
        for (int i = 0; i < 4; i++) {
            int idx = tid + i * 256;
            int r = idx >> 3, c = (idx & 7) << 2;
            float4 v = make_float4(0.f, 0.f, 0.f, 0.f);
            if (arow[i]) v = *(const float4*)(arow[i] + k0 + c);
            As[r][c + 0] = __uint_as_float(f2tf(v.x));
            As[r][c + 1] = __uint_as_float(f2tf(v.y));
            As[r][c + 2] = __uint_as_float(f2tf(v.z));
            As[r][c + 3] = __uint_as_float(f2tf(v.w));
        }
        /* load B tile 32x64 */
#pragma unroll
        for (int i = 0; i < 2; i++) {
            int idx = tid + i * 256;
            int r = idx >> 4, c = (idx & 15) << 2;
            float4 v = *(const float4*)(Wp + (size_t)(k0 + r) * N + n0 + c);
            Bs[r][c + 0] = __uint_as_float(f2tf(v.x));
            Bs[r][c + 1] = __uint_as_float(f2tf(v.y));
            Bs[r][c + 2] = __uint_as_float(f2tf(v.z));
            Bs[r][c + 3] = __uint_as_float(f2tf(v.w));
        }
        __syncthreads();

#pragma unroll
        for (int kk = 0; kk < 32; kk += 8) {
            unsigned a[2][4];
#pragma unroll
            for (int i = 0; i < 2; i++) {
                int rb = wm * 32 + i * 16;
                a[i][0] = __float_as_uint(As[rb + g][kk + tq]);
                a[i][1] = __float_as_uint(As[rb + 8 + g][kk + tq]);
                a[i][2] = __float_as_uint(As[rb + g][kk + 4 + tq]);
                a[i][3] = __float_as_uint(As[rb + 8 + g][kk + 4 + tq]);
            }
            unsigned b[4][2];
#pragma unroll
            for (int j = 0; j < 4; j++) {
                int cb = wn * 32 + j * 8 + g;
                b[j][0] = __float_as_uint(Bs[kk + tq][cb]);
                b[j][1] = __float_as_uint(Bs[kk + 4 + tq][cb]);
            }
#pragma unroll
            for (int i = 0; i < 2; i++)
#pragma unroll
                for (int j = 0; j < 4; j++) mma_tf32(acc[i][j], a[i], b[j]);
        }
        __syncthreads();
    }

    /* epilogue + writeback */
#pragma unroll
    for (int i = 0; i < 2; i++) {
        int r_lo = m0 + wm * 32 + i * 16 + g;
        int r_hi = r_lo + 8;
#pragma unroll
        for (int j = 0; j < 4; j++) {
            int n = n0 + wn * 32 + j * 8 + (tq << 1);
            float bn0 = bp[n], bn1 = bp[n + 1];
#pragma unroll
            for (int h = 0; h < 2; h++) {
                int m = h ? r_hi : r_lo;
                if (m >= cnt) continue;
                float v0 = acc[i][j][h * 2 + 0] + bn0;
                float v1 = acc[i][j][h * 2 + 1] + bn1;
                if (MODE == 2) {
                    v0 = 0.5f * v0 * (1.f + erff(v0 * 0.7071067811865475f));
                    v1 = 0.5f * v1 * (1.f + erff(v1 * 0.7071067811865475f));
                }
                float2 out = make_float2(v0, v1);
                if (MODE == 1)      *(float2*)(g_of   + (size_t)m * N + n) = out;
                else if (MODE == 2) *(float2*)(g_hid  + (size_t)(base + m) * N + n) = out;
                else                *(float2*)(g_eout + (size_t)(base + m) * N + n) = out;
            }
        }
    }
}

/* ---------------- router: one warp per token ---------------- */
__global__ void router_kernel(const float* __restrict__ rw,
                              const float* __restrict__ rb) {
    int t = blockIdx.x;
    int lane = threadIdx.x;
    const float* h = g_h + (size_t)t * Dm;
    float acc[Em];
#pragma unroll
    for (int e = 0; e < Em; e++) acc[e] = 0.f;

    for (int k = lane; k < Dm; k += 32) {
        float hv = h[k];
        const float* r = rw + k * Em;
#pragma unroll
        for (int e = 0; e < Em; e++) acc[e] += hv * r[e];
    }
#pragma unroll
    for (int e = 0; e < Em; e++)
        for (int o = 16; o; o >>= 1)
            acc[e] += __shfl_down_sync(0xffffffffu, acc[e], o);

    if (lane == 0) {
        float best = -1e30f, second = -1e30f;
        int bi = 0, si = 0;
#pragma unroll
        for (int e = 0; e < Em; e++) {
            float l = acc[e] + rb[e];
            if (l > best)       { second = best; si = bi; best = l; bi = e; }
            else if (l > second){ second = l; si = e; }
        }
        float e1 = expf(second - best);
        float inv = 1.f / (1.f + e1);
        g_top_idx[2 * t]     = bi;
        g_top_idx[2 * t + 1] = si;
        g_top_w[2 * t]       = inv;
        g_top_w[2 * t + 1]   = e1 * inv;
    }
}

__global__ void hist_kernel() {
    int t = blockIdx.x * blockDim.x + threadIdx.x;
    if (t < NT) {
        atomicAdd(&g_counts[g_top_idx[2 * t]], 1);
        atomicAdd(&g_counts[g_top_idx[2 * t + 1]], 1);
    }
}

__global__ void scan_kernel() {
    if (threadIdx.x == 0) {
        int off = 0;
        for (int e = 0; e < Em; e++) {
            g_offsets[e] = off;
            g_cursor[e]  = off;
            off += g_counts[e];
        }
    }
}

__global__ void scatter_kernel() {
    int t = blockIdx.x * blockDim.x + threadIdx.x;
    if (t < NT) {
        for (int k = 0; k < 2; k++) {
            int e = g_top_idx[2 * t + k];
            int slot = atomicAdd(&g_cursor[e], 1);
            g_slot_token[slot] = t;
            g_tok_slot[2 * t + k] = slot;
        }
    }
}

/* ---------------- combine top-2 expert outputs (deterministic) ------------ */
__global__ void combine_kernel() {
    int i = blockIdx.x * blockDim.x + threadIdx.x;
    if (i >= NT * Dm) return;
    int t = i >> 9, d = i & 511;
    int s0 = g_tok_slot[2 * t], s1 = g_tok_slot[2 * t + 1];
    g_moe[i] = g_top_w[2 * t]     * g_eout[(size_t)s0 * Dm + d]
             + g_top_w[2 * t + 1] * g_eout[(size_t)s1 * Dm + d];
}

/* ---------------- LayerNorm + residual ---------------- */
__global__ void ln_kernel(const float* __restrict__ x,
                          const float* __restrict__ gg,
                          const float* __restrict__ bb,
                          float* __restrict__ out) {
    int row = blockIdx.x;              /* 0 .. B*S-1 */
    int tid = threadIdx.x;             /* 128 threads */
    const float* v = g_ot + (size_t)row * Dm;

    float loc[4];
    float s = 0.f;
#pragma unroll
    for (int i = 0; i < 4; i++) {
        loc[i] = v[tid + i * 128];
        s += loc[i];
    }

    __shared__ float red[4];
    for (int o = 16; o; o >>= 1) s += __shfl_down_sync(0xffffffffu, s, o);
    if ((tid & 31) == 0) red[tid >> 5] = s;
    __syncthreads();
    float mu = (red[0] + red[1] + red[2] + red[3]) * (1.f / 512.f);
    __syncthreads();

    float q = 0.f;
#pragma unroll
    for (int i = 0; i < 4; i++) {
        float dd = loc[i] - mu;
        q += dd * dd;
    }
    for (int o = 16; o; o >>= 1) q += __shfl_down_sync(0xffffffffu, q, o);
    if ((tid & 31) == 0) red[tid >> 5] = q;
    __syncthreads();
    float var = (red[0] + red[1] + red[2] + red[3]) * (1.f / 512.f);
    float rs = rsqrtf(var + 1e-5f);

#pragma unroll
    for (int i = 0; i < 4; i++) {
        int d = tid + i * 128;
        size_t o = (size_t)row * Dm + d;
        out[o] = (loc[i] - mu) * rs * gg[d] + bb[d] + x[o];
    }
}

/* ---------------- launch ---------------- */
extern "C" void kernel_launch(void* const* d_in, const int* in_sizes, int n_in,
                              void* d_out, int out_size) {
    const float* x        = (const float*)d_in[0];
    const float* pin_w    = (const float*)d_in[1];
    const float* pin_b    = (const float*)d_in[2];
    const float* router_w = (const float*)d_in[3];
    const float* router_b = (const float*)d_in[4];
    const float* w1       = (const float*)d_in[5];
    const float* b1       = (const float*)d_in[6];
    const float* w2       = (const float*)d_in[7];
    const float* b2       = (const float*)d_in[8];
    const float* pout_w   = (const float*)d_in[9];
    const float* pout_b   = (const float*)d_in[10];
    const float* ln_g     = (const float*)d_in[11];
    const float* ln_b     = (const float*)d_in[12];
    float* out = (float*)d_out;

    const int MB = (NT + 127) / 128;   /* 129 M-tiles for tf32 kernels */

    setup_kernel<<<16, 256>>>();
    fft_fwd_kernel<<<Bn * Dm, 256>>>(x);
    gemm_pin_fp32_kernel<<<dim3(512 / 64, (NT + 63) / 64), 256>>>(pin_w, pin_b);
    router_kernel<<<NT, 32>>>(router_w, router_b);
    hist_kernel<<<(NT + 255) / 256, 256>>>();
    scan_kernel<<<1, 1>>>();
    scatter_kernel<<<(NT + 255) / 256, 256>>>();
    gemm_tf32_kernel<2><<<dim3(DFF / 64, MB, Em), 256>>>(w1, b1);
    gemm_tf32_kernel<3><<<dim3(Dm / 64, MB, Em), 256>>>(w2, b2);
    combine_kernel<<<(NT * Dm + 255) / 256, 256>>>();
    gemm_tf32_kernel<1><<<dim3(1024 / 64, MB), 256>>>(pout_w, pout_b);
    fft_inv_kernel<<<Bn * Dm, 256>>>();
    ln_kernel<<<Bn * Sn, 128>>>(x, ln_g, ln_b, out);
}

// round 7
// speedup vs baseline: 2.3195x; 1.2441x over previous
#include <cuda_runtime.h>
#include <cstdint>

#define Bn   8
#define Sn   4096
#define Dm   512
#define Fn   2049
#define Em   8
#define DFF  2048
#define NT   (Bn * Fn)      /* 16392 tokens in frequency domain */
#define NSLOT (2 * NT)      /* 32784 token-expert slots */

/* ---------------- scratch (device globals; no runtime alloc allowed) -------- */
__device__ float g_xfri[16785408];   /* NT x 1024  (re | im) */
__device__ float g_h   [8392704];    /* NT x 512  (EXACT fp32 — router reads) */
__device__ float g_moe [8392704];    /* NT x 512  (tf32-rounded at combine) */
__device__ float g_of  [16785408];   /* NT x 1024 */
__device__ float g_ot  [16777216];   /* B x S x D */
__device__ float g_hid [67141632];   /* NSLOT x 2048 (tf32-rounded at store) */
__device__ float g_eout[16785408];   /* NSLOT x 512 */
__device__ float g_w1t [8388608];    /* tf32-rounded w1 */
__device__ float g_w2t [8388608];    /* tf32-rounded w2 */
__device__ float g_poutt[524288];    /* tf32-rounded pout_w */
__device__ float2 g_tw [4096];       /* twiddle table: index = half + pos */
__device__ int   g_top_idx[NT * 2];
__device__ float g_top_w [NT * 2];
__device__ int   g_counts[Em];
__device__ int   g_offsets[Em];
__device__ int   g_cursor[Em];
__device__ int   g_slot_token[NSLOT];
__device__ int   g_tok_slot[NT * 2];

__device__ __forceinline__ unsigned f2tf(float f) {
    unsigned u;
    asm("cvt.rna.tf32.f32 %0, %1;" : "=r"(u) : "f"(f));
    return u;
}

/* ---------------- setup: zero counts + build twiddle table ---------------- */
__global__ void setup_kernel() {
    int i = blockIdx.x * blockDim.x + threadIdx.x;
    if (i < Em) g_counts[i] = 0;
    if (i >= 1 && i < 4096) {
        int half = 1 << (31 - __clz(i));
        int pos  = i - half;
        float ang = -6.283185307179586f * (float)pos / (float)(2 * half);
        float sn, cs;
        sincosf(ang, &sn, &cs);
        g_tw[i] = make_float2(cs, sn);
    }
}

/* ---------------- pre-round weights to tf32 (once per launch) ------------- */
__global__ void preround_kernel(const float* __restrict__ w1,
                                const float* __restrict__ w2,
                                const float* __restrict__ pw) {
    int i = blockIdx.x * blockDim.x + threadIdx.x;
    if (i < 8388608) {
        g_w1t[i] = __uint_as_float(f2tf(w1[i]));
        g_w2t[i] = __uint_as_float(f2tf(w2[i]));
    }
    if (i < 524288) g_poutt[i] = __uint_as_float(f2tf(pw[i]));
}

/* skewed smem index: kills 2-way bank conflicts in butterfly stages */
#define IX(i) ((i) + ((i) >> 5))

/* ---------------- forward rfft: one block per (b, d) column ---------------- */
__global__ void fft_fwd_kernel(const float* __restrict__ x) {
    __shared__ float re[4224];
    __shared__ float im[4224];
    int col = blockIdx.x;
    int b = col >> 9, d = col & 511;
    int tid = threadIdx.x;

    for (int s = tid; s < 4096; s += 256) {
        int r = (int)(__brev((unsigned)s) >> 20);
        re[IX(r)] = x[((size_t)b * Sn + s) * Dm + d];
        im[IX(r)] = 0.f;
    }
    __syncthreads();

    for (int st = 1; st <= 12; ++st) {
        int half = 1 << (st - 1);
        for (int j = tid; j < 2048; j += 256) {
            int pos = j & (half - 1);
            int i0  = ((j >> (st - 1)) << st) + pos;
            int i1  = i0 + half;
            int a0 = IX(i0), a1 = IX(i1);
            float2 w = g_tw[half + pos];
            float cs = w.x, sn = w.y;
            float ur = re[a0], ui = im[a0];
            float vr = re[a1], vi = im[a1];
            float tr = vr * cs - vi * sn;
            float ti = vr * sn + vi * cs;
            re[a0] = ur + tr; im[a0] = ui + ti;
            re[a1] = ur - tr; im[a1] = ui - ti;
        }
        __syncthreads();
    }

    const float sc = 0.015625f;   /* 1/sqrt(4096) */
    for (int k = tid; k < Fn; k += 256) {
        size_t o = ((size_t)b * Fn + k) * 1024 + d;
        g_xfri[o]       = re[IX(k)] * sc;
        g_xfri[o + 512] = im[IX(k)] * sc;
    }
}

/* ---------------- inverse rfft ---------------- */
__global__ void fft_inv_kernel() {
    __shared__ float re[4224];
    __shared__ float im[4224];
    int col = blockIdx.x;
    int b = col >> 9, d = col & 511;
    int tid = threadIdx.x;

    for (int s = tid; s < 4096; s += 256) {
        float yr, yi;
        if (s <= 2048) {
            size_t o = ((size_t)b * Fn + s) * 1024 + d;
            yr = g_of[o];
            yi = g_of[o + 512];
        } else {
            int k2 = 4096 - s;
            size_t o = ((size_t)b * Fn + k2) * 1024 + d;
            yr =  g_of[o];
            yi = -g_of[o + 512];
        }
        int r = (int)(__brev((unsigned)s) >> 20);
        re[IX(r)] = yr;
        im[IX(r)] = yi;
    }
    __syncthreads();

    for (int st = 1; st <= 12; ++st) {
        int half = 1 << (st - 1);
        for (int j = tid; j < 2048; j += 256) {
            int pos = j & (half - 1);
            int i0  = ((j >> (st - 1)) << st) + pos;
            int i1  = i0 + half;
            int a0 = IX(i0), a1 = IX(i1);
            float2 w = g_tw[half + pos];
            float cs = w.x, sn = -w.y;   /* conjugate for inverse */
            float ur = re[a0], ui = im[a0];
            float vr = re[a1], vi = im[a1];
            float tr = vr * cs - vi * sn;
            float ti = vr * sn + vi * cs;
            re[a0] = ur + tr; im[a0] = ui + ti;
            re[a1] = ur - tr; im[a1] = ui - ti;
        }
        __syncthreads();
    }

    const float sc = 0.015625f;
    for (int s = tid; s < 4096; s += 256)
        g_ot[((size_t)b * Sn + s) * Dm + d] = re[IX(s)] * sc;
}

/* ---------------- exact fp32 GEMM for pin (routing must be bit-faithful) ----
   g_h = g_xfri @ pin_w + pin_b   (M=NT, K=1024, N=512), 64x64x16 tile       */
__global__ __launch_bounds__(256) void gemm_pin_fp32_kernel(
        const float* __restrict__ W, const float* __restrict__ bias) {
    constexpr int K = 1024, N = 512;
    const int M = NT;

    __shared__ __align__(16) float As[16][64];
    __shared__ __align__(16) float Bs[16][64];

    int tid = threadIdx.x;
    int tx = tid & 15, ty = tid >> 4;
    int m0 = blockIdx.y * 64, n0 = blockIdx.x * 64;
    int arow = tid >> 2, acol = (tid & 3) << 2;
    int brow = tid >> 4, bcol = (tid & 15) << 2;

    float c[4][4];
#pragma unroll
    for (int i = 0; i < 4; i++)
#pragma unroll
        for (int j = 0; j < 4; j++) c[i][j] = 0.f;

    int gm = m0 + arow;
    const float* Arow = (gm < M) ? (g_xfri + (size_t)gm * K) : nullptr;

    for (int k0 = 0; k0 < K; k0 += 16) {
        float4 av = make_float4(0.f, 0.f, 0.f, 0.f);
        if (Arow) av = *(const float4*)(Arow + k0 + acol);
        As[acol + 0][arow] = av.x;
        As[acol + 1][arow] = av.y;
        As[acol + 2][arow] = av.z;
        As[acol + 3][arow] = av.w;
        *(float4*)&Bs[brow][bcol] =
            *(const float4*)(W + (size_t)(k0 + brow) * N + n0 + bcol);
        __syncthreads();
#pragma unroll
        for (int kk = 0; kk < 16; ++kk) {
            float4 a  = *(const float4*)&As[kk][ty << 2];
            float4 bq = *(const float4*)&Bs[kk][tx << 2];
            float aa[4] = {a.x, a.y, a.z, a.w};
            float bb[4] = {bq.x, bq.y, bq.z, bq.w};
#pragma unroll
            for (int i = 0; i < 4; i++)
#pragma unroll
                for (int j = 0; j < 4; j++) c[i][j] += aa[i] * bb[j];
        }
        __syncthreads();
    }

#pragma unroll
    for (int i = 0; i < 4; i++) {
        int m = m0 + (ty << 2) + i;
        if (m < M) {
#pragma unroll
            for (int j = 0; j < 4; j++) {
                int n = n0 + (tx << 2) + j;
                g_h[(size_t)m * N + n] = c[i][j] + bias[n];
            }
        }
    }
}

/* ==================== pipelined tf32 tensor-core GEMM ====================
   Block tile 128(M) x 64(N) x 32(K), 128 threads = 4 warps (2x2).
   Warp tile 64x32 = 4x4 grid of mma.sync.m16n8k8 tf32 tiles.
   2-stage cp.async pipeline; XOR-swizzled smem (no padding, 48KB).
   Weights (B) pre-rounded to tf32; activations pre-rounded at producers
   except g_h (kept exact fp32 for the router) — MODE 2 cvts A on read.
   MODE 1: g_of  = g_moe  @ g_poutt + pout_b             (K=512,  N=1024)
   MODE 2: g_hid = gelu(gather(g_h) @ g_w1t + b1[e])     (K=512,  N=2048)
   MODE 3: g_eout= g_hid @ g_w2t + b2[e]                 (K=2048, N=512)  */

__device__ __forceinline__ void mma_tf32(float c[4], const unsigned a[4],
                                         const unsigned b[2]) {
    asm volatile(
        "mma.sync.aligned.m16n8k8.row.col.f32.tf32.tf32.f32 "
        "{%0,%1,%2,%3}, {%4,%5,%6,%7}, {%8,%9}, {%0,%1,%2,%3};\n"
        : "+f"(c[0]), "+f"(c[1]), "+f"(c[2]), "+f"(c[3])
        : "r"(a[0]), "r"(a[1]), "r"(a[2]), "r"(a[3]), "r"(b[0]), "r"(b[1]));
}

template <int MODE>
__global__ __launch_bounds__(128) void gemm_tf32_kernel(
        const float* __restrict__ bias) {
    constexpr int K = (MODE == 1) ? 512 : (MODE == 2) ? 512 : 2048;
    constexpr int N = (MODE == 1) ? 1024 : (MODE == 2) ? 2048 : 512;
    constexpr int NSTEP = K / 32;

    int e = 0, cnt = NT, base = 0;
    if (MODE >= 2) {
        e = blockIdx.z;
        cnt = g_counts[e];
        base = g_offsets[e];
    }
    int m0 = blockIdx.y * 128;
    if (m0 >= cnt) return;
    int n0 = blockIdx.x * 64;

    const float* Wg = (MODE == 1) ? g_poutt : (MODE == 2) ? g_w1t : g_w2t;
    const float* Wp = Wg + (MODE >= 2 ? (size_t)e * K * N : 0);
    const float* bp = bias + (MODE >= 2 ? (size_t)e * N : 0);

    __shared__ float As[2][128][32];
    __shared__ float Bs[2][32][64];

    int tid = threadIdx.x;
    int wid = tid >> 5, lane = tid & 31;
    int wm = wid >> 1, wn = wid & 1;
    int g = lane >> 2, tq = lane & 3;

    /* A loader: 1024 16B-chunks / 128 thr = 8 each. row=(tid>>3)+16i, chunk=tid&7 */
    int acx = tid & 7;
    int arbase = tid >> 3;
    int ascol = ((acx ^ (arbase & 7)) << 2);
    const float* aptr[8];
#pragma unroll
    for (int i = 0; i < 8; i++) {
        int m = m0 + arbase + i * 16;
        const float* p = nullptr;
        if (m < cnt) {
            if (MODE == 1)      p = g_moe + (size_t)m * K;
            else if (MODE == 2) p = g_h + (size_t)g_slot_token[base + m] * K;
            else                p = g_hid + (size_t)(base + m) * K;
        }
        aptr[i] = p;
    }
    /* B loader: 512 chunks / 128 thr = 4 each. row=(tid>>4)+8i, chunk=tid&15 */
    int bcx = tid & 15;
    int brbase = tid >> 4;
    int bscol = ((bcx ^ (brbase & 7)) << 2);

    uint32_t asb[2], bsb[2];
#pragma unroll
    for (int s = 0; s < 2; s++) {
        asb[s] = (uint32_t)__cvta_generic_to_shared(&As[s][0][0]);
        bsb[s] = (uint32_t)__cvta_generic_to_shared(&Bs[s][0][0]);
    }

    auto load_stage = [&](int st, int k0v) {
#pragma unroll
        for (int i = 0; i < 8; i++) {
            int r = arbase + i * 16;
            uint32_t dst = asb[st] + (uint32_t)((r * 32 + ascol) * 4);
            const float* src = aptr[i] ? (aptr[i] + k0v + acx * 4)
                                       : (const float*)g_moe;
            int sz = aptr[i] ? 16 : 0;
            asm volatile("cp.async.cg.shared.global [%0], [%1], 16, %2;"
                         :: "r"(dst), "l"(src), "r"(sz));
        }
#pragma unroll
        for (int i = 0; i < 4; i++) {
            int r = brbase + i * 8;
            uint32_t dst = bsb[st] + (uint32_t)((r * 64 + bscol) * 4);
            const float* src = Wp + (size_t)(k0v + r) * N + n0 + bcx * 4;
            asm volatile("cp.async.cg.shared.global [%0], [%1], 16;"
                         :: "r"(dst), "l"(src));
        }
    };

    float acc[4][4][4];
#pragma unroll
    for (int i = 0; i < 4; i++)
#pragma unroll
        for (int j = 0; j < 4; j++)
#pragma unroll
            for (int r = 0; r < 4; r++) acc[i][j][r] = 0.f;

    load_stage(0, 0);
    asm volatile("cp.async.commit_group;");

    for (int it = 0; it < NSTEP; ++it) {
        int cur = it & 1;
        if (it + 1 < NSTEP) {
            load_stage(cur ^ 1, (it + 1) * 32);
            asm volatile("cp.async.commit_group;");
            asm volatile("cp.async.wait_group 1;");
        } else {
            asm volatile("cp.async.wait_group 0;");
        }
        __syncthreads();

#pragma unroll
        for (int kk = 0; kk < 32; kk += 8) {
            int c0 = kk >> 2;
            unsigned a[4][4];
#pragma unroll
            for (int i = 0; i < 4; i++) {
                int r0 = wm * 64 + i * 16 + g;
                int ca  = ((c0 ^ g) << 2) | tq;
                int ca4 = (((c0 + 1) ^ g) << 2) | tq;
                float v0 = As[cur][r0][ca];
                float v1 = As[cur][r0 + 8][ca];
                float v2 = As[cur][r0][ca4];
                float v3 = As[cur][r0 + 8][ca4];
                if (MODE == 2) {
                    a[i][0] = f2tf(v0); a[i][1] = f2tf(v1);
                    a[i][2] = f2tf(v2); a[i][3] = f2tf(v3);
                } else {
                    a[i][0] = __float_as_uint(v0); a[i][1] = __float_as_uint(v1);
                    a[i][2] = __float_as_uint(v2); a[i][3] = __float_as_uint(v3);
                }
            }
            unsigned b[4][2];
#pragma unroll
            for (int j = 0; j < 4; j++) {
                int cx = wn * 8 + j * 2 + (g >> 2);
                int col0 = ((cx ^ tq) << 2) | (g & 3);
                int col1 = ((cx ^ (4 + tq)) << 2) | (g & 3);
                b[j][0] = __float_as_uint(Bs[cur][kk + tq][col0]);
                b[j][1] = __float_as_uint(Bs[cur][kk + 4 + tq][col1]);
            }
#pragma unroll
            for (int i = 0; i < 4; i++)
#pragma unroll
                for (int j = 0; j < 4; j++) mma_tf32(acc[i][j], a[i], b[j]);
        }
        __syncthreads();
    }

    /* epilogue + writeback */
#pragma unroll
    for (int i = 0; i < 4; i++) {
        int r_lo = m0 + wm * 64 + i * 16 + g;
#pragma unroll
        for (int j = 0; j < 4; j++) {
            int n = n0 + wn * 32 + j * 8 + (tq << 1);
            float bn0 = bp[n], bn1 = bp[n + 1];
#pragma unroll
            for (int h = 0; h < 2; h++) {
                int m = r_lo + h * 8;
                if (m >= cnt) continue;
                float v0 = acc[i][j][h * 2 + 0] + bn0;
                float v1 = acc[i][j][h * 2 + 1] + bn1;
                if (MODE == 2) {
                    v0 = 0.5f * v0 * (1.f + erff(v0 * 0.7071067811865475f));
                    v1 = 0.5f * v1 * (1.f + erff(v1 * 0.7071067811865475f));
                    /* pre-round for GEMM2's A path (same numerics as load-cvt) */
                    v0 = __uint_as_float(f2tf(v0));
                    v1 = __uint_as_float(f2tf(v1));
                    *(float2*)(g_hid + (size_t)(base + m) * N + n) =
                        make_float2(v0, v1);
                } else if (MODE == 1) {
                    *(float2*)(g_of + (size_t)m * N + n) = make_float2(v0, v1);
                } else {
                    *(float2*)(g_eout + (size_t)(base + m) * N + n) =
                        make_float2(v0, v1);
                }
            }
        }
    }
}

/* ---------------- router: one warp per token ---------------- */
__global__ void router_kernel(const float* __restrict__ rw,
                              const float* __restrict__ rb) {
    int t = blockIdx.x;
    int lane = threadIdx.x;
    const float* h = g_h + (size_t)t * Dm;
    float acc[Em];
#pragma unroll
    for (int e = 0; e < Em; e++) acc[e] = 0.f;

    for (int k = lane; k < Dm; k += 32) {
        float hv = h[k];
        const float* r = rw + k * Em;
#pragma unroll
        for (int e = 0; e < Em; e++) acc[e] += hv * r[e];
    }
#pragma unroll
    for (int e = 0; e < Em; e++)
        for (int o = 16; o; o >>= 1)
            acc[e] += __shfl_down_sync(0xffffffffu, acc[e], o);

    if (lane == 0) {
        float best = -1e30f, second = -1e30f;
        int bi = 0, si = 0;
#pragma unroll
        for (int e = 0; e < Em; e++) {
            float l = acc[e] + rb[e];
            if (l > best)       { second = best; si = bi; best = l; bi = e; }
            else if (l > second){ second = l; si = e; }
        }
        float e1 = expf(second - best);
        float inv = 1.f / (1.f + e1);
        g_top_idx[2 * t]     = bi;
        g_top_idx[2 * t + 1] = si;
        g_top_w[2 * t]       = inv;
        g_top_w[2 * t + 1]   = e1 * inv;
    }
}

__global__ void hist_kernel() {
    int t = blockIdx.x * blockDim.x + threadIdx.x;
    if (t < NT) {
        atomicAdd(&g_counts[g_top_idx[2 * t]], 1);
        atomicAdd(&g_counts[g_top_idx[2 * t + 1]], 1);
    }
}

__global__ void scan_kernel() {
    if (threadIdx.x == 0) {
        int off = 0;
        for (int e = 0; e < Em; e++) {
            g_offsets[e] = off;
            g_cursor[e]  = off;
            off += g_counts[e];
        }
    }
}

__global__ void scatter_kernel() {
    int t = blockIdx.x * blockDim.x + threadIdx.x;
    if (t < NT) {
        for (int k = 0; k < 2; k++) {
            int e = g_top_idx[2 * t + k];
            int slot = atomicAdd(&g_cursor[e], 1);
            g_slot_token[slot] = t;
            g_tok_slot[2 * t + k] = slot;
        }
    }
}

/* ---------------- combine top-2 expert outputs (deterministic) ------------
   writes tf32-rounded g_moe (pout GEMM A path needs no runtime cvt)        */
__global__ void combine_kernel() {
    int i = blockIdx.x * blockDim.x + threadIdx.x;
    if (i >= NT * Dm) return;
    int t = i >> 9, d = i & 511;
    int s0 = g_tok_slot[2 * t], s1 = g_tok_slot[2 * t + 1];
    float v = g_top_w[2 * t]     * g_eout[(size_t)s0 * Dm + d]
            + g_top_w[2 * t + 1] * g_eout[(size_t)s1 * Dm + d];
    g_moe[i] = __uint_as_float(f2tf(v));
}

/* ---------------- LayerNorm + residual ---------------- */
__global__ void ln_kernel(const float* __restrict__ x,
                          const float* __restrict__ gg,
                          const float* __restrict__ bb,
                          float* __restrict__ out) {
    int row = blockIdx.x;              /* 0 .. B*S-1 */
    int tid = threadIdx.x;             /* 128 threads */
    const float* v = g_ot + (size_t)row * Dm;

    float loc[4];
    float s = 0.f;
#pragma unroll
    for (int i = 0; i < 4; i++) {
        loc[i] = v[tid + i * 128];
        s += loc[i];
    }

    __shared__ float red[4];
    for (int o = 16; o; o >>= 1) s += __shfl_down_sync(0xffffffffu, s, o);
    if ((tid & 31) == 0) red[tid >> 5] = s;
    __syncthreads();
    float mu = (red[0] + red[1] + red[2] + red[3]) * (1.f / 512.f);
    __syncthreads();

    float q = 0.f;
#pragma unroll
    for (int i = 0; i < 4; i++) {
        float dd = loc[i] - mu;
        q += dd * dd;
    }
    for (int o = 16; o; o >>= 1) q += __shfl_down_sync(0xffffffffu, q, o);
    if ((tid & 31) == 0) red[tid >> 5] = q;
    __syncthreads();
    float var = (red[0] + red[1] + red[2] + red[3]) * (1.f / 512.f);
    float rs = rsqrtf(var + 1e-5f);

#pragma unroll
    for (int i = 0; i < 4; i++) {
        int d = tid + i * 128;
        size_t o = (size_t)row * Dm + d;
        out[o] = (loc[i] - mu) * rs * gg[d] + bb[d] + x[o];
    }
}

/* ---------------- launch ---------------- */
extern "C" void kernel_launch(void* const* d_in, const int* in_sizes, int n_in,
                              void* d_out, int out_size) {
    const float* x        = (const float*)d_in[0];
    const float* pin_w    = (const float*)d_in[1];
    const float* pin_b    = (const float*)d_in[2];
    const float* router_w = (const float*)d_in[3];
    const float* router_b = (const float*)d_in[4];
    const float* w1       = (const float*)d_in[5];
    const float* b1       = (const float*)d_in[6];
    const float* w2       = (const float*)d_in[7];
    const float* b2       = (const float*)d_in[8];
    const float* pout_w   = (const float*)d_in[9];
    const float* pout_b   = (const float*)d_in[10];
    const float* ln_g     = (const float*)d_in[11];
    const float* ln_b     = (const float*)d_in[12];
    float* out = (float*)d_out;

    const int MB = (NT + 127) / 128;   /* 129 M-tiles for tf32 kernels */

    setup_kernel<<<16, 256>>>();
    preround_kernel<<<32768, 256>>>(w1, w2, pout_w);
    fft_fwd_kernel<<<Bn * Dm, 256>>>(x);
    gemm_pin_fp32_kernel<<<dim3(512 / 64, (NT + 63) / 64), 256>>>(pin_w, pin_b);
    router_kernel<<<NT, 32>>>(router_w, router_b);
    hist_kernel<<<(NT + 255) / 256, 256>>>();
    scan_kernel<<<1, 1>>>();
    scatter_kernel<<<(NT + 255) / 256, 256>>>();
    gemm_tf32_kernel<2><<<dim3(DFF / 64, MB, Em), 128>>>(b1);
    gemm_tf32_kernel<3><<<dim3(Dm / 64, MB, Em), 128>>>(b2);
    combine_kernel<<<(NT * Dm + 255) / 256, 256>>>();
    gemm_tf32_kernel<1><<<dim3(1024 / 64, MB), 128>>>(pout_b);
    fft_inv_kernel<<<Bn * Dm, 256>>>();
    ln_kernel<<<Bn * Sn, 128>>>(x, ln_g, ln_b, out);
}

// round 8
// speedup vs baseline: 3.5175x; 1.5165x over previous
#include <cuda_runtime.h>
#include <cstdint>

#define Bn   8
#define Sn   4096
#define Dm   512
#define Fn   2049
#define Em   8
#define DFF  2048
#define NT   (Bn * Fn)      /* 16392 tokens in frequency domain */
#define NSLOT (2 * NT)      /* 32784 token-expert slots */

/* ---------------- scratch (device globals; no runtime alloc allowed) -------- */
__device__ float g_xfri[16785408];   /* NT x 1024  (re | im), EXACT fp32 */
__device__ float g_h   [8392704];    /* NT x 512  (tf32-rounded at pin epi) */
__device__ float g_moe [8392704];    /* NT x 512  (tf32-rounded at combine) */
__device__ float g_of  [16785408];   /* NT x 1024 */
__device__ float g_ot  [16777216];   /* B x S x D */
__device__ float g_hid [67141632];   /* NSLOT x 2048 (tf32-rounded at store) */
__device__ float g_eout[16785408];   /* NSLOT x 512 */
__device__ float g_w1t [8388608];    /* tf32-rounded w1 */
__device__ float g_w2t [8388608];    /* tf32-rounded w2 */
__device__ float g_poutt[524288];    /* tf32-rounded pout_w */
__device__ float g_pint [524288];    /* tf32-rounded pin_w */
__device__ float g_wr  [8192];       /* fused router weights pin_w @ router_w */
__device__ float g_br  [8];          /* fused router bias */
__device__ float2 g_tw [4096];       /* twiddle table: index = half + pos */
__device__ int   g_top_idx[NT * 2];
__device__ float g_top_w [NT * 2];
__device__ int   g_counts[Em];
__device__ int   g_offsets[Em];
__device__ int   g_cursor[Em];
__device__ int   g_slot_token[NSLOT];
__device__ int   g_tok_slot[NT * 2];

__device__ __forceinline__ unsigned f2tf(float f) {
    unsigned u;
    asm("cvt.rna.tf32.f32 %0, %1;" : "=r"(u) : "f"(f));
    return u;
}

/* ---------------- setup: zero counts + build twiddle table ---------------- */
__global__ void setup_kernel() {
    int i = blockIdx.x * blockDim.x + threadIdx.x;
    if (i < Em) g_counts[i] = 0;
    if (i >= 1 && i < 4096) {
        int half = 1 << (31 - __clz(i));
        int pos  = i - half;
        float ang = -6.283185307179586f * (float)pos / (float)(2 * half);
        float sn, cs;
        sincosf(ang, &sn, &cs);
        g_tw[i] = make_float2(cs, sn);
    }
}

/* ---------------- pre-round weights to tf32 (once per launch) ------------- */
__global__ void preround_kernel(const float* __restrict__ w1,
                                const float* __restrict__ w2,
                                const float* __restrict__ pw,
                                const float* __restrict__ piw) {
    int i = blockIdx.x * blockDim.x + threadIdx.x;
    if (i < 8388608) {
        g_w1t[i] = __uint_as_float(f2tf(w1[i]));
        g_w2t[i] = __uint_as_float(f2tf(w2[i]));
    }
    if (i < 524288) {
        g_poutt[i] = __uint_as_float(f2tf(pw[i]));
        g_pint[i]  = __uint_as_float(f2tf(piw[i]));
    }
}

/* ---------------- fused router weights: Wr = pin_w @ router_w ------------- */
__global__ void wr_kernel(const float* __restrict__ pin_w,
                          const float* __restrict__ pin_b,
                          const float* __restrict__ rw,
                          const float* __restrict__ rb) {
    int f = blockIdx.x, tid = threadIdx.x;
    if (f == 1024) {
        if (tid < 8) {
            float s = rb[tid];
            for (int d = 0; d < 512; d++) s += pin_b[d] * rw[d * 8 + tid];
            g_br[tid] = s;
        }
        return;
    }
    float acc[8] = {0.f, 0.f, 0.f, 0.f, 0.f, 0.f, 0.f, 0.f};
    for (int d = tid; d < 512; d += 128) {
        float pv = pin_w[f * 512 + d];
        const float* r = rw + d * 8;
#pragma unroll
        for (int e = 0; e < 8; e++) acc[e] += pv * r[e];
    }
    __shared__ float red[4][8];
#pragma unroll
    for (int e = 0; e < 8; e++)
        for (int o = 16; o; o >>= 1)
            acc[e] += __shfl_down_sync(0xffffffffu, acc[e], o);
    if ((tid & 31) == 0) {
#pragma unroll
        for (int e = 0; e < 8; e++) red[tid >> 5][e] = acc[e];
    }
    __syncthreads();
    if (tid < 8)
        g_wr[f * 8 + tid] = red[0][tid] + red[1][tid] + red[2][tid] + red[3][tid];
}

/* skewed smem index: kills 2-way bank conflicts in butterfly stages */
#define IX(i) ((i) + ((i) >> 5))

/* ---------------- forward rfft, two d-columns per block (two-for-one) ------
   z = x[:,d0] + i*x[:,d0+1]; FFT(z); Hermitian split recovers both spectra. */
__global__ void fft_fwd_kernel(const float* __restrict__ x) {
    __shared__ float re[4224];
    __shared__ float im[4224];
    int pr = blockIdx.x;
    int b = pr >> 8, d0 = (pr & 255) << 1;
    int tid = threadIdx.x;

    for (int s = tid; s < 4096; s += 256) {
        float2 v = *(const float2*)(x + ((size_t)b * Sn + s) * Dm + d0);
        int r = (int)(__brev((unsigned)s) >> 20);
        re[IX(r)] = v.x;
        im[IX(r)] = v.y;
    }
    __syncthreads();

    for (int st = 1; st <= 12; ++st) {
        int half = 1 << (st - 1);
        for (int j = tid; j < 2048; j += 256) {
            int pos = j & (half - 1);
            int i0  = ((j >> (st - 1)) << st) + pos;
            int i1  = i0 + half;
            int a0 = IX(i0), a1 = IX(i1);
            float2 w = g_tw[half + pos];
            float cs = w.x, sn = w.y;
            float ur = re[a0], ui = im[a0];
            float vr = re[a1], vi = im[a1];
            float tr = vr * cs - vi * sn;
            float ti = vr * sn + vi * cs;
            re[a0] = ur + tr; im[a0] = ui + ti;
            re[a1] = ur - tr; im[a1] = ui - ti;
        }
        __syncthreads();
    }

    const float sc = 0.5f * 0.015625f;   /* 0.5 (split) * 1/sqrt(4096) */
    for (int k = tid; k <= 2048; k += 256) {
        int k2 = (4096 - k) & 4095;
        float zr  = re[IX(k)],  zi  = im[IX(k)];
        float z2r = re[IX(k2)], z2i = im[IX(k2)];
        float xdr = (zr + z2r) * sc, xdi = (zi - z2i) * sc;
        float xer = (zi + z2i) * sc, xei = (z2r - zr) * sc;
        size_t o = ((size_t)b * Fn + k) * 1024 + d0;
        *(float2*)(g_xfri + o)       = make_float2(xdr, xer);
        *(float2*)(g_xfri + o + 512) = make_float2(xdi, xei);
    }
}

/* ---------------- inverse rfft, two d-columns per block --------------------
   Z = Xd + i*Xe (Hermitian-extended, DC/Nyquist imag zeroed to match numpy);
   out_d = Re(ifft(Z)), out_e = Im(ifft(Z)).                                 */
__global__ void fft_inv_kernel() {
    __shared__ float re[4224];
    __shared__ float im[4224];
    int pr = blockIdx.x;
    int b = pr >> 8, d0 = (pr & 255) << 1;
    int tid = threadIdx.x;

    for (int k = tid; k < 4096; k += 256) {
        float zr, zi;
        if (k <= 2048) {
            size_t o = ((size_t)b * Fn + k) * 1024 + d0;
            float2 vre = *(const float2*)(g_of + o);
            float2 vim = *(const float2*)(g_of + o + 512);
            float a = vre.x, c = vre.y, bb = vim.x, dd = vim.y;
            if (k == 0 || k == 2048) { bb = 0.f; dd = 0.f; }
            zr = a - dd;
            zi = bb + c;
        } else {
            int k2 = 4096 - k;
            size_t o = ((size_t)b * Fn + k2) * 1024 + d0;
            float2 vre = *(const float2*)(g_of + o);
            float2 vim = *(const float2*)(g_of + o + 512);
            float a = vre.x, c = vre.y, bb = vim.x, dd = vim.y;
            zr = a + dd;
            zi = c - bb;
        }
        int r = (int)(__brev((unsigned)k) >> 20);
        re[IX(r)] = zr;
        im[IX(r)] = zi;
    }
    __syncthreads();

    for (int st = 1; st <= 12; ++st) {
        int half = 1 << (st - 1);
        for (int j = tid; j < 2048; j += 256) {
            int pos = j & (half - 1);
            int i0  = ((j >> (st - 1)) << st) + pos;
            int i1  = i0 + half;
            int a0 = IX(i0), a1 = IX(i1);
            float2 w = g_tw[half + pos];
            float cs = w.x, sn = -w.y;   /* conjugate for inverse */
            float ur = re[a0], ui = im[a0];
            float vr = re[a1], vi = im[a1];
            float tr = vr * cs - vi * sn;
            float ti = vr * sn + vi * cs;
            re[a0] = ur + tr; im[a0] = ui + ti;
            re[a1] = ur - tr; im[a1] = ui - ti;
        }
        __syncthreads();
    }

    const float sc = 0.015625f;
    for (int s = tid; s < 4096; s += 256) {
        *(float2*)(g_ot + ((size_t)b * Sn + s) * Dm + d0) =
            make_float2(re[IX(s)] * sc, im[IX(s)] * sc);
    }
}

/* ==================== pipelined tf32 tensor-core GEMM ====================
   Block tile 128(M) x 64(N) x 32(K), 128 threads = 4 warps (2x2).
   Warp tile 64x32 = 4x4 grid of mma.sync.m16n8k8 tf32 tiles.
   2-stage cp.async pipeline; XOR-swizzled smem (no padding, 48KB).
   MODE 0: g_h   = cvt(g_xfri) @ g_pint + pin_b          (K=1024, N=512)
   MODE 1: g_of  = g_moe  @ g_poutt + pout_b             (K=512,  N=1024)
   MODE 2: g_hid = gelu(gather(g_h) @ g_w1t + b1[e])     (K=512,  N=2048)
   MODE 3: g_eout= g_hid @ g_w2t + b2[e]                 (K=2048, N=512)  */

__device__ __forceinline__ void mma_tf32(float c[4], const unsigned a[4],
                                         const unsigned b[2]) {
    asm volatile(
        "mma.sync.aligned.m16n8k8.row.col.f32.tf32.tf32.f32 "
        "{%0,%1,%2,%3}, {%4,%5,%6,%7}, {%8,%9}, {%0,%1,%2,%3};\n"
        : "+f"(c[0]), "+f"(c[1]), "+f"(c[2]), "+f"(c[3])
        : "r"(a[0]), "r"(a[1]), "r"(a[2]), "r"(a[3]), "r"(b[0]), "r"(b[1]));
}

template <int MODE>
__global__ __launch_bounds__(128) void gemm_tf32_kernel(
        const float* __restrict__ bias) {
    constexpr int K = (MODE == 0) ? 1024 : (MODE == 3) ? 2048 : 512;
    constexpr int N = (MODE == 0) ? 512 : (MODE == 1) ? 1024
                    : (MODE == 2) ? 2048 : 512;
    constexpr int NSTEP = K / 32;

    int e = 0, cnt = NT, base = 0;
    if (MODE >= 2) {
        e = blockIdx.z;
        cnt = g_counts[e];
        base = g_offsets[e];
    }
    int m0 = blockIdx.y * 128;
    if (m0 >= cnt) return;
    int n0 = blockIdx.x * 64;

    const float* Wg = (MODE == 0) ? g_pint : (MODE == 1) ? g_poutt
                    : (MODE == 2) ? g_w1t : g_w2t;
    const float* Wp = Wg + (MODE >= 2 ? (size_t)e * K * N : 0);
    const float* bp = bias + (MODE >= 2 ? (size_t)e * N : 0);

    __shared__ float As[2][128][32];
    __shared__ float Bs[2][32][64];

    int tid = threadIdx.x;
    int wid = tid >> 5, lane = tid & 31;
    int wm = wid >> 1, wn = wid & 1;
    int g = lane >> 2, tq = lane & 3;

    /* A loader: 1024 16B-chunks / 128 thr = 8 each. row=(tid>>3)+16i, chunk=tid&7 */
    int acx = tid & 7;
    int arbase = tid >> 3;
    int ascol = ((acx ^ (arbase & 7)) << 2);
    const float* aptr[8];
#pragma unroll
    for (int i = 0; i < 8; i++) {
        int m = m0 + arbase + i * 16;
        const float* p = nullptr;
        if (m < cnt) {
            if (MODE == 0)      p = g_xfri + (size_t)m * K;
            else if (MODE == 1) p = g_moe + (size_t)m * K;
            else if (MODE == 2) p = g_h + (size_t)g_slot_token[base + m] * K;
            else                p = g_hid + (size_t)(base + m) * K;
        }
        aptr[i] = p;
    }
    /* B loader: 512 chunks / 128 thr = 4 each. row=(tid>>4)+8i, chunk=tid&15 */
    int bcx = tid & 15;
    int brbase = tid >> 4;
    int bscol = ((bcx ^ (brbase & 7)) << 2);

    uint32_t asb[2], bsb[2];
#pragma unroll
    for (int s = 0; s < 2; s++) {
        asb[s] = (uint32_t)__cvta_generic_to_shared(&As[s][0][0]);
        bsb[s] = (uint32_t)__cvta_generic_to_shared(&Bs[s][0][0]);
    }

    auto load_stage = [&](int st, int k0v) {
#pragma unroll
        for (int i = 0; i < 8; i++) {
            int r = arbase + i * 16;
            uint32_t dst = asb[st] + (uint32_t)((r * 32 + ascol) * 4);
            const float* src = aptr[i] ? (aptr[i] + k0v + acx * 4)
                                       : (const float*)g_moe;
            int sz = aptr[i] ? 16 : 0;
            asm volatile("cp.async.cg.shared.global [%0], [%1], 16, %2;"
                         :: "r"(dst), "l"(src), "r"(sz));
        }
#pragma unroll
        for (int i = 0; i < 4; i++) {
            int r = brbase + i * 8;
            uint32_t dst = bsb[st] + (uint32_t)((r * 64 + bscol) * 4);
            const float* src = Wp + (size_t)(k0v + r) * N + n0 + bcx * 4;
            asm volatile("cp.async.cg.shared.global [%0], [%1], 16;"
                         :: "r"(dst), "l"(src));
        }
    };

    float acc[4][4][4];
#pragma unroll
    for (int i = 0; i < 4; i++)
#pragma unroll
        for (int j = 0; j < 4; j++)
#pragma unroll
            for (int r = 0; r < 4; r++) acc[i][j][r] = 0.f;

    load_stage(0, 0);
    asm volatile("cp.async.commit_group;");

    for (int it = 0; it < NSTEP; ++it) {
        int cur = it & 1;
        if (it + 1 < NSTEP) {
            load_stage(cur ^ 1, (it + 1) * 32);
            asm volatile("cp.async.commit_group;");
            asm volatile("cp.async.wait_group 1;");
        } else {
            asm volatile("cp.async.wait_group 0;");
        }
        __syncthreads();

#pragma unroll
        for (int kk = 0; kk < 32; kk += 8) {
            int c0 = kk >> 2;
            unsigned a[4][4];
#pragma unroll
            for (int i = 0; i < 4; i++) {
                int r0 = wm * 64 + i * 16 + g;
                int ca  = ((c0 ^ g) << 2) | tq;
                int ca4 = (((c0 + 1) ^ g) << 2) | tq;
                float v0 = As[cur][r0][ca];
                float v1 = As[cur][r0 + 8][ca];
                float v2 = As[cur][r0][ca4];
                float v3 = As[cur][r0 + 8][ca4];
                if (MODE == 0) {
                    a[i][0] = f2tf(v0); a[i][1] = f2tf(v1);
                    a[i][2] = f2tf(v2); a[i][3] = f2tf(v3);
                } else {
                    a[i][0] = __float_as_uint(v0); a[i][1] = __float_as_uint(v1);
                    a[i][2] = __float_as_uint(v2); a[i][3] = __float_as_uint(v3);
                }
            }
            unsigned b[4][2];
#pragma unroll
            for (int j = 0; j < 4; j++) {
                int cx = wn * 8 + j * 2 + (g >> 2);
                int col0 = ((cx ^ tq) << 2) | (g & 3);
                int col1 = ((cx ^ (4 + tq)) << 2) | (g & 3);
                b[j][0] = __float_as_uint(Bs[cur][kk + tq][col0]);
                b[j][1] = __float_as_uint(Bs[cur][kk + 4 + tq][col1]);
            }
#pragma unroll
            for (int i = 0; i < 4; i++)
#pragma unroll
                for (int j = 0; j < 4; j++) mma_tf32(acc[i][j], a[i], b[j]);
        }
        __syncthreads();
    }

    /* epilogue + writeback */
#pragma unroll
    for (int i = 0; i < 4; i++) {
        int r_lo = m0 + wm * 64 + i * 16 + g;
#pragma unroll
        for (int j = 0; j < 4; j++) {
            int n = n0 + wn * 32 + j * 8 + (tq << 1);
            float bn0 = bp[n], bn1 = bp[n + 1];
#pragma unroll
            for (int h = 0; h < 2; h++) {
                int m = r_lo + h * 8;
                if (m >= cnt) continue;
                float v0 = acc[i][j][h * 2 + 0] + bn0;
                float v1 = acc[i][j][h * 2 + 1] + bn1;
                if (MODE == 0) {
                    /* pre-round h for MoE GEMM1's A path */
                    v0 = __uint_as_float(f2tf(v0));
                    v1 = __uint_as_float(f2tf(v1));
                    *(float2*)(g_h + (size_t)m * N + n) = make_float2(v0, v1);
                } else if (MODE == 2) {
                    v0 = 0.5f * v0 * (1.f + erff(v0 * 0.7071067811865475f));
                    v1 = 0.5f * v1 * (1.f + erff(v1 * 0.7071067811865475f));
                    v0 = __uint_as_float(f2tf(v0));
                    v1 = __uint_as_float(f2tf(v1));
                    *(float2*)(g_hid + (size_t)(base + m) * N + n) =
                        make_float2(v0, v1);
                } else if (MODE == 1) {
                    *(float2*)(g_of + (size_t)m * N + n) = make_float2(v0, v1);
                } else {
                    *(float2*)(g_eout + (size_t)(base + m) * N + n) =
                        make_float2(v0, v1);
                }
            }
        }
    }
}

/* ---------------- fused router: logits from exact g_xfri, then top-2 ------ */
__global__ __launch_bounds__(256) void logits_topk_kernel() {
    __shared__ float Ws[8][1024];   /* transposed Wr: Ws[e][k], 32KB */
    int tid = threadIdx.x;
    for (int i = tid; i < 8192; i += 256)
        Ws[i & 7][i >> 3] = g_wr[i];
    __syncthreads();

    int wid = tid >> 5, lane = tid & 31;
    int t = blockIdx.x * 8 + wid;
    if (t >= NT) return;

    const float4* xr = (const float4*)(g_xfri + (size_t)t * 1024);
    float acc[8] = {0.f, 0.f, 0.f, 0.f, 0.f, 0.f, 0.f, 0.f};
#pragma unroll
    for (int it = 0; it < 8; ++it) {
        float4 v = xr[it * 32 + lane];
        int k = it * 128 + lane * 4;
#pragma unroll
        for (int e = 0; e < 8; e++) {
            acc[e] += v.x * Ws[e][k]     + v.y * Ws[e][k + 1]
                    + v.z * Ws[e][k + 2] + v.w * Ws[e][k + 3];
        }
    }
#pragma unroll
    for (int e = 0; e < 8; e++)
        for (int o = 16; o; o >>= 1)
            acc[e] += __shfl_down_sync(0xffffffffu, acc[e], o);

    if (lane == 0) {
        float best = -1e30f, second = -1e30f;
        int bi = 0, si = 0;
#pragma unroll
        for (int e = 0; e < 8; e++) {
            float l = acc[e] + g_br[e];
            if (l > best)       { second = best; si = bi; best = l; bi = e; }
            else if (l > second){ second = l; si = e; }
        }
        float e1 = expf(second - best);
        float inv = 1.f / (1.f + e1);
        g_top_idx[2 * t]     = bi;
        g_top_idx[2 * t + 1] = si;
        g_top_w[2 * t]       = inv;
        g_top_w[2 * t + 1]   = e1 * inv;
    }
}

__global__ void hist_kernel() {
    int t = blockIdx.x * blockDim.x + threadIdx.x;
    if (t < NT) {
        atomicAdd(&g_counts[g_top_idx[2 * t]], 1);
        atomicAdd(&g_counts[g_top_idx[2 * t + 1]], 1);
    }
}

__global__ void scan_kernel() {
    if (threadIdx.x == 0) {
        int off = 0;
        for (int e = 0; e < Em; e++) {
            g_offsets[e] = off;
            g_cursor[e]  = off;
            off += g_counts[e];
        }
    }
}

__global__ void scatter_kernel() {
    int t = blockIdx.x * blockDim.x + threadIdx.x;
    if (t < NT) {
        for (int k = 0; k < 2; k++) {
            int e = g_top_idx[2 * t + k];
            int slot = atomicAdd(&g_cursor[e], 1);
            g_slot_token[slot] = t;
            g_tok_slot[2 * t + k] = slot;
        }
    }
}

/* ---------------- combine top-2 expert outputs (deterministic) ------------
   writes tf32-rounded g_moe (pout GEMM A path needs no runtime cvt)        */
__global__ void combine_kernel() {
    int i = blockIdx.x * blockDim.x + threadIdx.x;
    if (i >= NT * Dm) return;
    int t = i >> 9, d = i & 511;
    int s0 = g_tok_slot[2 * t], s1 = g_tok_slot[2 * t + 1];
    float v = g_top_w[2 * t]     * g_eout[(size_t)s0 * Dm + d]
            + g_top_w[2 * t + 1] * g_eout[(size_t)s1 * Dm + d];
    g_moe[i] = __uint_as_float(f2tf(v));
}

/* ---------------- LayerNorm + residual ---------------- */
__global__ void ln_kernel(const float* __restrict__ x,
                          const float* __restrict__ gg,
                          const float* __restrict__ bb,
                          float* __restrict__ out) {
    int row = blockIdx.x;              /* 0 .. B*S-1 */
    int tid = threadIdx.x;             /* 128 threads */
    const float* v = g_ot + (size_t)row * Dm;

    float loc[4];
    float s = 0.f;
#pragma unroll
    for (int i = 0; i < 4; i++) {
        loc[i] = v[tid + i * 128];
        s += loc[i];
    }

    __shared__ float red[4];
    for (int o = 16; o; o >>= 1) s += __shfl_down_sync(0xffffffffu, s, o);
    if ((tid & 31) == 0) red[tid >> 5] = s;
    __syncthreads();
    float mu = (red[0] + red[1] + red[2] + red[3]) * (1.f / 512.f);
    __syncthreads();

    float q = 0.f;
#pragma unroll
    for (int i = 0; i < 4; i++) {
        float dd = loc[i] - mu;
        q += dd * dd;
    }
    for (int o = 16; o; o >>= 1) q += __shfl_down_sync(0xffffffffu, q, o);
    if ((tid & 31) == 0) red[tid >> 5] = q;
    __syncthreads();
    float var = (red[0] + red[1] + red[2] + red[3]) * (1.f / 512.f);
    float rs = rsqrtf(var + 1e-5f);

#pragma unroll
    for (int i = 0; i < 4; i++) {
        int d = tid + i * 128;
        size_t o = (size_t)row * Dm + d;
        out[o] = (loc[i] - mu) * rs * gg[d] + bb[d] + x[o];
    }
}

/* ---------------- launch ---------------- */
extern "C" void kernel_launch(void* const* d_in, const int* in_sizes, int n_in,
                              void* d_out, int out_size) {
    const float* x        = (const float*)d_in[0];
    const float* pin_w    = (const float*)d_in[1];
    const float* pin_b    = (const float*)d_in[2];
    const float* router_w = (const float*)d_in[3];
    const float* router_b = (const float*)d_in[4];
    const float* w1       = (const float*)d_in[5];
    const float* b1       = (const float*)d_in[6];
    const float* w2       = (const float*)d_in[7];
    const float* b2       = (const float*)d_in[8];
    const float* pout_w   = (const float*)d_in[9];
    const float* pout_b   = (const float*)d_in[10];
    const float* ln_g     = (const float*)d_in[11];
    const float* ln_b     = (const float*)d_in[12];
    float* out = (float*)d_out;

    const int MB = (NT + 127) / 128;   /* 129 M-tiles for tf32 kernels */

    setup_kernel<<<16, 256>>>();
    preround_kernel<<<32768, 256>>>(w1, w2, pout_w, pin_w);
    wr_kernel<<<1025, 128>>>(pin_w, pin_b, router_w, router_b);
    fft_fwd_kernel<<<Bn * 256, 256>>>(x);
    gemm_tf32_kernel<0><<<dim3(512 / 64, MB), 128>>>(pin_b);
    logits_topk_kernel<<<(NT + 7) / 8, 256>>>();
    hist_kernel<<<(NT + 255) / 256, 256>>>();
    scan_kernel<<<1, 1>>>();
    scatter_kernel<<<(NT + 255) / 256, 256>>>();
    gemm_tf32_kernel<2><<<dim3(DFF / 64, MB, Em), 128>>>(b1);
    gemm_tf32_kernel<3><<<dim3(Dm / 64, MB, Em), 128>>>(b2);
    combine_kernel<<<(NT * Dm + 255) / 256, 256>>>();
    gemm_tf32_kernel<1><<<dim3(1024 / 64, MB), 128>>>(pout_b);
    fft_inv_kernel<<<Bn * 256, 256>>>();
    ln_kernel<<<Bn * Sn, 128>>>(x, ln_g, ln_b, out);
}

// round 9
// speedup vs baseline: 3.6570x; 1.0397x over previous
#include <cuda_runtime.h>
#include <cstdint>

#define Bn   8
#define Sn   4096
#define Dm   512
#define Fn   2049
#define Em   8
#define DFF  2048
#define NT   (Bn * Fn)      /* 16392 tokens in frequency domain */
#define NSLOT (2 * NT)      /* 32784 token-expert slots */

/* ---------------- scratch (device globals; no runtime alloc allowed) -------- */
__device__ float g_xfri[16785408];   /* NT x 1024  (re | im), EXACT fp32 */
__device__ float g_h   [8392704];    /* NT x 512  (tf32-rounded at pin epi) */
__device__ float g_moe [8392704];    /* NT x 512  (tf32-rounded at combine) */
__device__ float g_of  [16785408];   /* NT x 1024 */
__device__ float g_ot  [16777216];   /* B x S x D */
__device__ float g_hid [67141632];   /* NSLOT x 2048 (tf32-rounded at store) */
__device__ float g_eout[16785408];   /* NSLOT x 512 */
__device__ float g_w1t [8388608];    /* tf32-rounded w1 */
__device__ float g_w2t [8388608];    /* tf32-rounded w2 */
__device__ float g_poutt[524288];    /* tf32-rounded pout_w */
__device__ float g_pint [524288];    /* tf32-rounded pin_w */
__device__ float g_wr  [8192];       /* fused router weights pin_w @ router_w */
__device__ float g_br  [8];          /* fused router bias */
__device__ float2 g_tw [4096];       /* twiddle table: index = half + pos */
__device__ int   g_top_idx[NT * 2];
__device__ float g_top_w [NT * 2];
__device__ int   g_counts[Em];
__device__ int   g_offsets[Em];
__device__ int   g_cursor[Em];
__device__ int   g_slot_token[NSLOT];
__device__ int   g_tok_slot[NT * 2];

__device__ __forceinline__ unsigned f2tf(float f) {
    unsigned u;
    asm("cvt.rna.tf32.f32 %0, %1;" : "=r"(u) : "f"(f));
    return u;
}

/* ---------------- setup: zero counts + build twiddle table ---------------- */
__global__ void setup_kernel() {
    int i = blockIdx.x * blockDim.x + threadIdx.x;
    if (i < Em) g_counts[i] = 0;
    if (i >= 1 && i < 4096) {
        int half = 1 << (31 - __clz(i));
        int pos  = i - half;
        float ang = -6.283185307179586f * (float)pos / (float)(2 * half);
        float sn, cs;
        sincosf(ang, &sn, &cs);
        g_tw[i] = make_float2(cs, sn);
    }
}

/* ---------------- pre-round weights to tf32 (once per launch) ------------- */
__global__ void preround_kernel(const float* __restrict__ w1,
                                const float* __restrict__ w2,
                                const float* __restrict__ pw,
                                const float* __restrict__ piw) {
    int i = blockIdx.x * blockDim.x + threadIdx.x;
    if (i < 8388608) {
        g_w1t[i] = __uint_as_float(f2tf(w1[i]));
        g_w2t[i] = __uint_as_float(f2tf(w2[i]));
    }
    if (i < 524288) {
        g_poutt[i] = __uint_as_float(f2tf(pw[i]));
        g_pint[i]  = __uint_as_float(f2tf(piw[i]));
    }
}

/* ---------------- fused router weights: Wr = pin_w @ router_w ------------- */
__global__ void wr_kernel(const float* __restrict__ pin_w,
                          const float* __restrict__ pin_b,
                          const float* __restrict__ rw,
                          const float* __restrict__ rb) {
    int f = blockIdx.x, tid = threadIdx.x;
    if (f == 1024) {
        if (tid < 8) {
            float s = rb[tid];
            for (int d = 0; d < 512; d++) s += pin_b[d] * rw[d * 8 + tid];
            g_br[tid] = s;
        }
        return;
    }
    float acc[8] = {0.f, 0.f, 0.f, 0.f, 0.f, 0.f, 0.f, 0.f};
    for (int d = tid; d < 512; d += 128) {
        float pv = pin_w[f * 512 + d];
        const float* r = rw + d * 8;
#pragma unroll
        for (int e = 0; e < 8; e++) acc[e] += pv * r[e];
    }
    __shared__ float red[4][8];
#pragma unroll
    for (int e = 0; e < 8; e++)
        for (int o = 16; o; o >>= 1)
            acc[e] += __shfl_down_sync(0xffffffffu, acc[e], o);
    if ((tid & 31) == 0) {
#pragma unroll
        for (int e = 0; e < 8; e++) red[tid >> 5][e] = acc[e];
    }
    __syncthreads();
    if (tid < 8)
        g_wr[f * 8 + tid] = red[0][tid] + red[1][tid] + red[2][tid] + red[3][tid];
}

/* skewed smem index: kills 2-way bank conflicts in butterfly stages */
#define IX(i) ((i) + ((i) >> 5))

/* base-4 digit reversal of a 12-bit index: bitrev then swap adjacent bits */
__device__ __forceinline__ unsigned dr4(unsigned s) {
    unsigned t = __brev(s) >> 20;
    return ((t & 0x555u) << 1) | ((t >> 1) & 0x555u);
}

/* radix-4 DIT butterfly macro body (INV: 0 = forward, 1 = inverse) */
template <int INV>
__device__ __forceinline__ void radix4_stages(float* re, float* im, int tid) {
#pragma unroll
    for (int st = 0; st < 6; ++st) {
        int Q = 1 << (2 * st);
        for (int j = tid; j < 1024; j += 256) {
            int pos = j & (Q - 1);
            int base = (j >> (2 * st)) << (2 * st + 2);
            int i0 = base + pos;
            int a0 = IX(i0), a1 = IX(i0 + Q), a2 = IX(i0 + 2 * Q),
                a3 = IX(i0 + 3 * Q);
            float2 w1 = g_tw[2 * Q + pos];   /* e^{-2pi i pos/L}, L=4Q */
            float2 w2 = g_tw[Q + pos];       /* e^{-2pi i 2pos/L} */
            float w1i = INV ? -w1.y : w1.y;
            float w2i = INV ? -w2.y : w2.y;
            float w3r = w1.x * w2.x - w1i * w2i;
            float w3i = w1.x * w2i + w1i * w2.x;
            float t0r = re[a0], t0i = im[a0];
            float xr = re[a1], xi = im[a1];
            float t1r = xr * w1.x - xi * w1i, t1i = xr * w1i + xi * w1.x;
            xr = re[a2]; xi = im[a2];
            float t2r = xr * w2.x - xi * w2i, t2i = xr * w2i + xi * w2.x;
            xr = re[a3]; xi = im[a3];
            float t3r = xr * w3r - xi * w3i, t3i = xr * w3i + xi * w3r;
            float s0r = t0r + t2r, s0i = t0i + t2i;
            float s1r = t0r - t2r, s1i = t0i - t2i;
            float s2r = t1r + t3r, s2i = t1i + t3i;
            float s3r = t1r - t3r, s3i = t1i - t3i;
            re[a0] = s0r + s2r; im[a0] = s0i + s2i;
            re[a2] = s0r - s2r; im[a2] = s0i - s2i;
            if (!INV) {
                re[a1] = s1r + s3i; im[a1] = s1i - s3r;   /* s1 - i s3 */
                re[a3] = s1r - s3i; im[a3] = s1i + s3r;   /* s1 + i s3 */
            } else {
                re[a1] = s1r - s3i; im[a1] = s1i + s3r;   /* s1 + i s3 */
                re[a3] = s1r + s3i; im[a3] = s1i - s3r;   /* s1 - i s3 */
            }
        }
        __syncthreads();
    }
}

/* ---------------- forward rfft, two d-columns per block (two-for-one) ------
   z = x[:,d0] + i*x[:,d0+1]; FFT(z); Hermitian split recovers both spectra. */
__global__ void fft_fwd_kernel(const float* __restrict__ x) {
    __shared__ float re[4224];
    __shared__ float im[4224];
    int pr = blockIdx.x;
    int b = pr >> 8, d0 = (pr & 255) << 1;
    int tid = threadIdx.x;

    for (int s = tid; s < 4096; s += 256) {
        float2 v = *(const float2*)(x + ((size_t)b * Sn + s) * Dm + d0);
        unsigned r = dr4((unsigned)s);
        re[IX(r)] = v.x;
        im[IX(r)] = v.y;
    }
    __syncthreads();

    radix4_stages<0>(re, im, tid);

    const float sc = 0.5f * 0.015625f;   /* 0.5 (split) * 1/sqrt(4096) */
    for (int k = tid; k <= 2048; k += 256) {
        int k2 = (4096 - k) & 4095;
        float zr  = re[IX(k)],  zi  = im[IX(k)];
        float z2r = re[IX(k2)], z2i = im[IX(k2)];
        float xdr = (zr + z2r) * sc, xdi = (zi - z2i) * sc;
        float xer = (zi + z2i) * sc, xei = (z2r - zr) * sc;
        size_t o = ((size_t)b * Fn + k) * 1024 + d0;
        *(float2*)(g_xfri + o)       = make_float2(xdr, xer);
        *(float2*)(g_xfri + o + 512) = make_float2(xdi, xei);
    }
}

/* ---------------- inverse rfft, two d-columns per block --------------------
   Z = Xd + i*Xe (Hermitian-extended, DC/Nyquist imag zeroed to match numpy);
   out_d = Re(ifft(Z)), out_e = Im(ifft(Z)).                                 */
__global__ void fft_inv_kernel() {
    __shared__ float re[4224];
    __shared__ float im[4224];
    int pr = blockIdx.x;
    int b = pr >> 8, d0 = (pr & 255) << 1;
    int tid = threadIdx.x;

    for (int k = tid; k < 4096; k += 256) {
        float zr, zi;
        if (k <= 2048) {
            size_t o = ((size_t)b * Fn + k) * 1024 + d0;
            float2 vre = *(const float2*)(g_of + o);
            float2 vim = *(const float2*)(g_of + o + 512);
            float a = vre.x, c = vre.y, bb = vim.x, dd = vim.y;
            if (k == 0 || k == 2048) { bb = 0.f; dd = 0.f; }
            zr = a - dd;
            zi = bb + c;
        } else {
            int k2 = 4096 - k;
            size_t o = ((size_t)b * Fn + k2) * 1024 + d0;
            float2 vre = *(const float2*)(g_of + o);
            float2 vim = *(const float2*)(g_of + o + 512);
            float a = vre.x, c = vre.y, bb = vim.x, dd = vim.y;
            zr = a + dd;
            zi = c - bb;
        }
        unsigned r = dr4((unsigned)k);
        re[IX(r)] = zr;
        im[IX(r)] = zi;
    }
    __syncthreads();

    radix4_stages<1>(re, im, tid);

    const float sc = 0.015625f;
    for (int s = tid; s < 4096; s += 256) {
        *(float2*)(g_ot + ((size_t)b * Sn + s) * Dm + d0) =
            make_float2(re[IX(s)] * sc, im[IX(s)] * sc);
    }
}

/* ==================== pipelined tf32 tensor-core GEMM ====================
   Block tile 128(M) x 64(N) x 32(K), 128 threads = 4 warps (2x2).
   Warp tile 64x32 = 4x4 grid of mma.sync.m16n8k8 tf32 tiles.
   2-stage cp.async pipeline; XOR-swizzled smem (no padding, 48KB).
   MODE 0: g_h   = cvt(g_xfri) @ g_pint + pin_b          (K=1024, N=512)
   MODE 1: g_of  = g_moe  @ g_poutt + pout_b             (K=512,  N=1024)
   MODE 2: g_hid = gelu(gather(g_h) @ g_w1t + b1[e])     (K=512,  N=2048)
   MODE 3: g_eout= g_hid @ g_w2t + b2[e]                 (K=2048, N=512)  */

__device__ __forceinline__ void mma_tf32(float c[4], const unsigned a[4],
                                         const unsigned b[2]) {
    asm volatile(
        "mma.sync.aligned.m16n8k8.row.col.f32.tf32.tf32.f32 "
        "{%0,%1,%2,%3}, {%4,%5,%6,%7}, {%8,%9}, {%0,%1,%2,%3};\n"
        : "+f"(c[0]), "+f"(c[1]), "+f"(c[2]), "+f"(c[3])
        : "r"(a[0]), "r"(a[1]), "r"(a[2]), "r"(a[3]), "r"(b[0]), "r"(b[1]));
}

template <int MODE>
__global__ __launch_bounds__(128) void gemm_tf32_kernel(
        const float* __restrict__ bias) {
    constexpr int K = (MODE == 0) ? 1024 : (MODE == 3) ? 2048 : 512;
    constexpr int N = (MODE == 0) ? 512 : (MODE == 1) ? 1024
                    : (MODE == 2) ? 2048 : 512;
    constexpr int NSTEP = K / 32;

    int e = 0, cnt = NT, base = 0;
    if (MODE >= 2) {
        e = blockIdx.z;
        cnt = g_counts[e];
        base = g_offsets[e];
    }
    int m0 = blockIdx.y * 128;
    if (m0 >= cnt) return;
    int n0 = blockIdx.x * 64;

    const float* Wg = (MODE == 0) ? g_pint : (MODE == 1) ? g_poutt
                    : (MODE == 2) ? g_w1t : g_w2t;
    const float* Wp = Wg + (MODE >= 2 ? (size_t)e * K * N : 0);
    const float* bp = bias + (MODE >= 2 ? (size_t)e * N : 0);

    __shared__ float As[2][128][32];
    __shared__ float Bs[2][32][64];

    int tid = threadIdx.x;
    int wid = tid >> 5, lane = tid & 31;
    int wm = wid >> 1, wn = wid & 1;
    int g = lane >> 2, tq = lane & 3;

    /* A loader: 1024 16B-chunks / 128 thr = 8 each. row=(tid>>3)+16i, chunk=tid&7 */
    int acx = tid & 7;
    int arbase = tid >> 3;
    int ascol = ((acx ^ (arbase & 7)) << 2);
    const float* aptr[8];
#pragma unroll
    for (int i = 0; i < 8; i++) {
        int m = m0 + arbase + i * 16;
        const float* p = nullptr;
        if (m < cnt) {
            if (MODE == 0)      p = g_xfri + (size_t)m * K;
            else if (MODE == 1) p = g_moe + (size_t)m * K;
            else if (MODE == 2) p = g_h + (size_t)g_slot_token[base + m] * K;
            else                p = g_hid + (size_t)(base + m) * K;
        }
        aptr[i] = p;
    }
    /* B loader: 512 chunks / 128 thr = 4 each. row=(tid>>4)+8i, chunk=tid&15 */
    int bcx = tid & 15;
    int brbase = tid >> 4;
    int bscol = ((bcx ^ (brbase & 7)) << 2);

    uint32_t asb[2], bsb[2];
#pragma unroll
    for (int s = 0; s < 2; s++) {
        asb[s] = (uint32_t)__cvta_generic_to_shared(&As[s][0][0]);
        bsb[s] = (uint32_t)__cvta_generic_to_shared(&Bs[s][0][0]);
    }

    auto load_stage = [&](int st, int k0v) {
#pragma unroll
        for (int i = 0; i < 8; i++) {
            int r = arbase + i * 16;
            uint32_t dst = asb[st] + (uint32_t)((r * 32 + ascol) * 4);
            const float* src = aptr[i] ? (aptr[i] + k0v + acx * 4)
                                       : (const float*)g_moe;
            int sz = aptr[i] ? 16 : 0;
            asm volatile("cp.async.cg.shared.global [%0], [%1], 16, %2;"
                         :: "r"(dst), "l"(src), "r"(sz));
        }
#pragma unroll
        for (int i = 0; i < 4; i++) {
            int r = brbase + i * 8;
            uint32_t dst = bsb[st] + (uint32_t)((r * 64 + bscol) * 4);
            const float* src = Wp + (size_t)(k0v + r) * N + n0 + bcx * 4;
            asm volatile("cp.async.cg.shared.global [%0], [%1], 16;"
                         :: "r"(dst), "l"(src));
        }
    };

    float acc[4][4][4];
#pragma unroll
    for (int i = 0; i < 4; i++)
#pragma unroll
        for (int j = 0; j < 4; j++)
#pragma unroll
            for (int r = 0; r < 4; r++) acc[i][j][r] = 0.f;

    load_stage(0, 0);
    asm volatile("cp.async.commit_group;");

    for (int it = 0; it < NSTEP; ++it) {
        int cur = it & 1;
        if (it + 1 < NSTEP) {
            load_stage(cur ^ 1, (it + 1) * 32);
            asm volatile("cp.async.commit_group;");
            asm volatile("cp.async.wait_group 1;");
        } else {
            asm volatile("cp.async.wait_group 0;");
        }
        __syncthreads();

#pragma unroll
        for (int kk = 0; kk < 32; kk += 8) {
            int c0 = kk >> 2;
            unsigned a[4][4];
#pragma unroll
            for (int i = 0; i < 4; i++) {
                int r0 = wm * 64 + i * 16 + g;
                int ca  = ((c0 ^ g) << 2) | tq;
                int ca4 = (((c0 + 1) ^ g) << 2) | tq;
                float v0 = As[cur][r0][ca];
                float v1 = As[cur][r0 + 8][ca];
                float v2 = As[cur][r0][ca4];
                float v3 = As[cur][r0 + 8][ca4];
                if (MODE == 0) {
                    a[i][0] = f2tf(v0); a[i][1] = f2tf(v1);
                    a[i][2] = f2tf(v2); a[i][3] = f2tf(v3);
                } else {
                    a[i][0] = __float_as_uint(v0); a[i][1] = __float_as_uint(v1);
                    a[i][2] = __float_as_uint(v2); a[i][3] = __float_as_uint(v3);
                }
            }
            unsigned b[4][2];
#pragma unroll
            for (int j = 0; j < 4; j++) {
                int cx = wn * 8 + j * 2 + (g >> 2);
                int col0 = ((cx ^ tq) << 2) | (g & 3);
                int col1 = ((cx ^ (4 + tq)) << 2) | (g & 3);
                b[j][0] = __float_as_uint(Bs[cur][kk + tq][col0]);
                b[j][1] = __float_as_uint(Bs[cur][kk + 4 + tq][col1]);
            }
#pragma unroll
            for (int i = 0; i < 4; i++)
#pragma unroll
                for (int j = 0; j < 4; j++) mma_tf32(acc[i][j], a[i], b[j]);
        }
        __syncthreads();
    }

    /* epilogue + writeback */
#pragma unroll
    for (int i = 0; i < 4; i++) {
        int r_lo = m0 + wm * 64 + i * 16 + g;
#pragma unroll
        for (int j = 0; j < 4; j++) {
            int n = n0 + wn * 32 + j * 8 + (tq << 1);
            float bn0 = bp[n], bn1 = bp[n + 1];
#pragma unroll
            for (int h = 0; h < 2; h++) {
                int m = r_lo + h * 8;
                if (m >= cnt) continue;
                float v0 = acc[i][j][h * 2 + 0] + bn0;
                float v1 = acc[i][j][h * 2 + 1] + bn1;
                if (MODE == 0) {
                    /* pre-round h for MoE GEMM1's A path */
                    v0 = __uint_as_float(f2tf(v0));
                    v1 = __uint_as_float(f2tf(v1));
                    *(float2*)(g_h + (size_t)m * N + n) = make_float2(v0, v1);
                } else if (MODE == 2) {
                    v0 = 0.5f * v0 * (1.f + erff(v0 * 0.7071067811865475f));
                    v1 = 0.5f * v1 * (1.f + erff(v1 * 0.7071067811865475f));
                    v0 = __uint_as_float(f2tf(v0));
                    v1 = __uint_as_float(f2tf(v1));
                    *(float2*)(g_hid + (size_t)(base + m) * N + n) =
                        make_float2(v0, v1);
                } else if (MODE == 1) {
                    *(float2*)(g_of + (size_t)m * N + n) = make_float2(v0, v1);
                } else {
                    *(float2*)(g_eout + (size_t)(base + m) * N + n) =
                        make_float2(v0, v1);
                }
            }
        }
    }
}

/* ---------------- fused router: logits from exact g_xfri, top-2, hist ----- */
__global__ __launch_bounds__(256) void logits_topk_kernel() {
    __shared__ float Ws[8][1024];   /* transposed Wr: Ws[e][k], 32KB */
    int tid = threadIdx.x;
    for (int i = tid; i < 8192; i += 256)
        Ws[i & 7][i >> 3] = g_wr[i];
    __syncthreads();

    int wid = tid >> 5, lane = tid & 31;
    int t = blockIdx.x * 8 + wid;
    if (t >= NT) return;

    const float4* xr = (const float4*)(g_xfri + (size_t)t * 1024);
    float acc[8] = {0.f, 0.f, 0.f, 0.f, 0.f, 0.f, 0.f, 0.f};
#pragma unroll
    for (int it = 0; it < 8; ++it) {
        float4 v = xr[it * 32 + lane];
        int k = it * 128 + lane * 4;
#pragma unroll
        for (int e = 0; e < 8; e++) {
            acc[e] += v.x * Ws[e][k]     + v.y * Ws[e][k + 1]
                    + v.z * Ws[e][k + 2] + v.w * Ws[e][k + 3];
        }
    }
#pragma unroll
    for (int e = 0; e < 8; e++)
        for (int o = 16; o; o >>= 1)
            acc[e] += __shfl_down_sync(0xffffffffu, acc[e], o);

    if (lane == 0) {
        float best = -1e30f, second = -1e30f;
        int bi = 0, si = 0;
#pragma unroll
        for (int e = 0; e < 8; e++) {
            float l = acc[e] + g_br[e];
            if (l > best)       { second = best; si = bi; best = l; bi = e; }
            else if (l > second){ second = l; si = e; }
        }
        float e1 = expf(second - best);
        float inv = 1.f / (1.f + e1);
        g_top_idx[2 * t]     = bi;
        g_top_idx[2 * t + 1] = si;
        g_top_w[2 * t]       = inv;
        g_top_w[2 * t + 1]   = e1 * inv;
        atomicAdd(&g_counts[bi], 1);
        atomicAdd(&g_counts[si], 1);
    }
}

__global__ void scan_kernel() {
    if (threadIdx.x == 0) {
        int off = 0;
        for (int e = 0; e < Em; e++) {
            g_offsets[e] = off;
            g_cursor[e]  = off;
            off += g_counts[e];
        }
    }
}

__global__ void scatter_kernel() {
    int t = blockIdx.x * blockDim.x + threadIdx.x;
    if (t < NT) {
        for (int k = 0; k < 2; k++) {
            int e = g_top_idx[2 * t + k];
            int slot = atomicAdd(&g_cursor[e], 1);
            g_slot_token[slot] = t;
            g_tok_slot[2 * t + k] = slot;
        }
    }
}

/* ---------------- combine top-2 expert outputs (deterministic) ------------
   writes tf32-rounded g_moe (pout GEMM A path needs no runtime cvt)        */
__global__ void combine_kernel() {
    int i = blockIdx.x * blockDim.x + threadIdx.x;
    if (i >= NT * Dm) return;
    int t = i >> 9, d = i & 511;
    int s0 = g_tok_slot[2 * t], s1 = g_tok_slot[2 * t + 1];
    float v = g_top_w[2 * t]     * g_eout[(size_t)s0 * Dm + d]
            + g_top_w[2 * t + 1] * g_eout[(size_t)s1 * Dm + d];
    g_moe[i] = __uint_as_float(f2tf(v));
}

/* ---------------- LayerNorm + residual ---------------- */
__global__ void ln_kernel(const float* __restrict__ x,
                          const float* __restrict__ gg,
                          const float* __restrict__ bb,
                          float* __restrict__ out) {
    int row = blockIdx.x;              /* 0 .. B*S-1 */
    int tid = threadIdx.x;             /* 128 threads */
    const float* v = g_ot + (size_t)row * Dm;

    float loc[4];
    float s = 0.f;
#pragma unroll
    for (int i = 0; i < 4; i++) {
        loc[i] = v[tid + i * 128];
        s += loc[i];
    }

    __shared__ float red[4];
    for (int o = 16; o; o >>= 1) s += __shfl_down_sync(0xffffffffu, s, o);
    if ((tid & 31) == 0) red[tid >> 5] = s;
    __syncthreads();
    float mu = (red[0] + red[1] + red[2] + red[3]) * (1.f / 512.f);
    __syncthreads();

    float q = 0.f;
#pragma unroll
    for (int i = 0; i < 4; i++) {
        float dd = loc[i] - mu;
        q += dd * dd;
    }
    for (int o = 16; o; o >>= 1) q += __shfl_down_sync(0xffffffffu, q, o);
    if ((tid & 31) == 0) red[tid >> 5] = q;
    __syncthreads();
    float var = (red[0] + red[1] + red[2] + red[3]) * (1.f / 512.f);
    float rs = rsqrtf(var + 1e-5f);

#pragma unroll
    for (int i = 0; i < 4; i++) {
        int d = tid + i * 128;
        size_t o = (size_t)row * Dm + d;
        out[o] = (loc[i] - mu) * rs * gg[d] + bb[d] + x[o];
    }
}

/* ---------------- launch ---------------- */
extern "C" void kernel_launch(void* const* d_in, const int* in_sizes, int n_in,
                              void* d_out, int out_size) {
    const float* x        = (const float*)d_in[0];
    const float* pin_w    = (const float*)d_in[1];
    const float* pin_b    = (const float*)d_in[2];
    const float* router_w = (const float*)d_in[3];
    const float* router_b = (const float*)d_in[4];
    const float* w1       = (const float*)d_in[5];
    const float* b1       = (const float*)d_in[6];
    const float* w2       = (const float*)d_in[7];
    const float* b2       = (const float*)d_in[8];
    const float* pout_w   = (const float*)d_in[9];
    const float* pout_b   = (const float*)d_in[10];
    const float* ln_g     = (const float*)d_in[11];
    const float* ln_b     = (const float*)d_in[12];
    float* out = (float*)d_out;

    const int MB = (NT + 127) / 128;   /* 129 M-tiles for tf32 kernels */

    setup_kernel<<<16, 256>>>();
    preround_kernel<<<32768, 256>>>(w1, w2, pout_w, pin_w);
    wr_kernel<<<1025, 128>>>(pin_w, pin_b, router_w, router_b);
    fft_fwd_kernel<<<Bn * 256, 256>>>(x);
    gemm_tf32_kernel<0><<<dim3(512 / 64, MB), 128>>>(pin_b);
    logits_topk_kernel<<<(NT + 7) / 8, 256>>>();
    scan_kernel<<<1, 1>>>();
    scatter_kernel<<<(NT + 255) / 256, 256>>>();
    gemm_tf32_kernel<2><<<dim3(DFF / 64, MB, Em), 128>>>(b1);
    gemm_tf32_kernel<3><<<dim3(Dm / 64, MB, Em), 128>>>(b2);
    combine_kernel<<<(NT * Dm + 255) / 256, 256>>>();
    gemm_tf32_kernel<1><<<dim3(1024 / 64, MB), 128>>>(pout_b);
    fft_inv_kernel<<<Bn * 256, 256>>>();
    ln_kernel<<<Bn * Sn, 128>>>(x, ln_g, ln_b, out);
}

// round 10
// speedup vs baseline: 4.0039x; 1.0948x over previous
#include <cuda_runtime.h>
#include <cstdint>

#define Bn   8
#define Sn   4096
#define Dm   512
#define Fn   2049
#define Em   8
#define DFF  2048
#define NT   (Bn * Fn)      /* 16392 tokens in frequency domain */
#define NSLOT (2 * NT)      /* 32784 token-expert slots */

/* ---------------- scratch (device globals; no runtime alloc allowed) -------- */
__device__ float g_xfri[16785408];   /* NT x 1024  (re | im), EXACT fp32 */
__device__ float g_h   [8392704];    /* NT x 512  (tf32-rounded at pin epi) */
__device__ float g_moe [8392704];    /* NT x 512  (tf32-rounded at combine) */
__device__ float g_of  [16785408];   /* NT x 1024 */
__device__ float g_ot  [16777216];   /* B x S x D */
__device__ float g_hid [67141632];   /* NSLOT x 2048 (tf32-rounded at store) */
__device__ float g_eout[16785408];   /* NSLOT x 512 */
__device__ float g_w1t [8388608];    /* tf32-rounded w1 */
__device__ float g_w2t [8388608];    /* tf32-rounded w2 */
__device__ float g_poutt[524288];    /* tf32-rounded pout_w */
__device__ float g_pint [524288];    /* tf32-rounded pin_w */
__device__ float g_wr  [8192];       /* fused router weights pin_w @ router_w */
__device__ float g_br  [8];          /* fused router bias */
__device__ float2 g_tw [4096];       /* twiddle table: index = half + pos */
__device__ int   g_top_idx[NT * 2];
__device__ float g_top_w [NT * 2];
__device__ int   g_counts[Em];
__device__ int   g_offsets[Em];
__device__ int   g_cursor[Em];
__device__ int   g_slot_token[NSLOT];
__device__ int   g_tok_slot[NT * 2];

__device__ __forceinline__ unsigned f2tf(float f) {
    unsigned u;
    asm("cvt.rna.tf32.f32 %0, %1;" : "=r"(u) : "f"(f));
    return u;
}

/* ---------------- setup: zero counts + build twiddle table ---------------- */
__global__ void setup_kernel() {
    int i = blockIdx.x * blockDim.x + threadIdx.x;
    if (i < Em) g_counts[i] = 0;
    if (i >= 1 && i < 4096) {
        int half = 1 << (31 - __clz(i));
        int pos  = i - half;
        float ang = -6.283185307179586f * (float)pos / (float)(2 * half);
        float sn, cs;
        sincosf(ang, &sn, &cs);
        g_tw[i] = make_float2(cs, sn);
    }
}

/* ---------------- pre-round weights to tf32 (once per launch) ------------- */
__global__ void preround_kernel(const float* __restrict__ w1,
                                const float* __restrict__ w2,
                                const float* __restrict__ pw,
                                const float* __restrict__ piw) {
    int i = blockIdx.x * blockDim.x + threadIdx.x;
    if (i < 8388608) {
        g_w1t[i] = __uint_as_float(f2tf(w1[i]));
        g_w2t[i] = __uint_as_float(f2tf(w2[i]));
    }
    if (i < 524288) {
        g_poutt[i] = __uint_as_float(f2tf(pw[i]));
        g_pint[i]  = __uint_as_float(f2tf(piw[i]));
    }
}

/* ---------------- fused router weights: Wr = pin_w @ router_w ------------- */
__global__ void wr_kernel(const float* __restrict__ pin_w,
                          const float* __restrict__ pin_b,
                          const float* __restrict__ rw,
                          const float* __restrict__ rb) {
    int f = blockIdx.x, tid = threadIdx.x;
    if (f == 1024) {
        if (tid < 8) {
            float s = rb[tid];
            for (int d = 0; d < 512; d++) s += pin_b[d] * rw[d * 8 + tid];
            g_br[tid] = s;
        }
        return;
    }
    float acc[8] = {0.f, 0.f, 0.f, 0.f, 0.f, 0.f, 0.f, 0.f};
    for (int d = tid; d < 512; d += 128) {
        float pv = pin_w[f * 512 + d];
        const float* r = rw + d * 8;
#pragma unroll
        for (int e = 0; e < 8; e++) acc[e] += pv * r[e];
    }
    __shared__ float red[4][8];
#pragma unroll
    for (int e = 0; e < 8; e++)
        for (int o = 16; o; o >>= 1)
            acc[e] += __shfl_down_sync(0xffffffffu, acc[e], o);
    if ((tid & 31) == 0) {
#pragma unroll
        for (int e = 0; e < 8; e++) red[tid >> 5][e] = acc[e];
    }
    __syncthreads();
    if (tid < 8)
        g_wr[f * 8 + tid] = red[0][tid] + red[1][tid] + red[2][tid] + red[3][tid];
}

/* skewed smem index: kills 2-way bank conflicts in butterfly stages */
#define IX(i) ((i) + ((i) >> 5))

/* base-4 digit reversal of a 12-bit index: bitrev then swap adjacent bits */
__device__ __forceinline__ unsigned dr4(unsigned s) {
    unsigned t = __brev(s) >> 20;
    return ((t & 0x555u) << 1) | ((t >> 1) & 0x555u);
}

/* one radix-4 DIT butterfly on register elements 0, S, 2S, 3S */
template <int INV, int S>
__device__ __forceinline__ void bfly4(float* xr, float* xi,
                                      float2 w1, float2 w2) {
    float w1i = INV ? -w1.y : w1.y;
    float w2i = INV ? -w2.y : w2.y;
    float w3r = w1.x * w2.x - w1i * w2i;
    float w3i = w1.x * w2i + w1i * w2.x;
    float t0r = xr[0], t0i = xi[0];
    float t1r = xr[S] * w1.x - xi[S] * w1i;
    float t1i = xr[S] * w1i + xi[S] * w1.x;
    float t2r = xr[2 * S] * w2.x - xi[2 * S] * w2i;
    float t2i = xr[2 * S] * w2i + xi[2 * S] * w2.x;
    float t3r = xr[3 * S] * w3r - xi[3 * S] * w3i;
    float t3i = xr[3 * S] * w3i + xi[3 * S] * w3r;
    float s0r = t0r + t2r, s0i = t0i + t2i;
    float s1r = t0r - t2r, s1i = t0i - t2i;
    float s2r = t1r + t3r, s2i = t1i + t3i;
    float s3r = t1r - t3r, s3i = t1i - t3i;
    xr[0] = s0r + s2r;     xi[0] = s0i + s2i;
    xr[2 * S] = s0r - s2r; xi[2 * S] = s0i - s2i;
    if (!INV) {
        xr[S] = s1r + s3i;     xi[S] = s1i - s3r;     /* s1 - i s3 */
        xr[3 * S] = s1r - s3i; xi[3 * S] = s1i + s3r; /* s1 + i s3 */
    } else {
        xr[S] = s1r - s3i;     xi[S] = s1i + s3r;
        xr[3 * S] = s1r + s3i; xi[3 * S] = s1i - s3r;
    }
}

/* fused pair of radix-4 stages on a 16-register group.
   Registers hold elements g + k*Q (k=0..15), pos = g mod Q.
   Stage A: global stage with quarter-stride Q  (same twiddles for all 4)
   Stage B: global stage with quarter-stride 4Q (twiddles depend on sub-pos) */
template <int INV>
__device__ __forceinline__ void pair16(float* xr, float* xi, int Q, int pos) {
    float2 wA1 = g_tw[2 * Q + pos];
    float2 wA2 = g_tw[Q + pos];
#pragma unroll
    for (int b = 0; b < 4; b++)
        bfly4<INV, 1>(xr + 4 * b, xi + 4 * b, wA1, wA2);
#pragma unroll
    for (int c = 0; c < 4; c++) {
        float2 wB1 = g_tw[8 * Q + pos + c * Q];
        float2 wB2 = g_tw[4 * Q + pos + c * Q];
        bfly4<INV, 4>(xr + c, xi + c, wB1, wB2);
    }
}

/* ---------------- forward rfft, two d-columns per block (two-for-one) ------
   z = x[:,d0] + i*x[:,d0+1]; FFT(z); Hermitian split recovers both spectra. */
__global__ __launch_bounds__(256) void fft_fwd_kernel(const float* __restrict__ x) {
    __shared__ float re[4224];
    __shared__ float im[4224];
    int pr = blockIdx.x;
    int b = pr >> 8, d0 = (pr & 255) << 1;
    int tid = threadIdx.x;

    float xr[16], xi[16];

    /* direct digit-reversed load into registers (pair-0 grouping: 16t+k) */
#pragma unroll
    for (int k = 0; k < 16; k++) {
        unsigned s = dr4((unsigned)(16 * tid + k));
        float2 v = *(const float2*)(x + ((size_t)b * Sn + s) * Dm + d0);
        xr[k] = v.x;
        xi[k] = v.y;
    }
    pair16<0>(xr, xi, 1, 0);
#pragma unroll
    for (int k = 0; k < 16; k++) {
        int i = 16 * tid + k;
        re[IX(i)] = xr[k];
        im[IX(i)] = xi[k];
    }
    __syncthreads();

    /* pair 1: Q=16, elements g + 16k, in-place per group */
    {
        int pos = tid & 15, g = ((tid >> 4) << 8) + pos;
#pragma unroll
        for (int k = 0; k < 16; k++) {
            int i = g + (k << 4);
            xr[k] = re[IX(i)];
            xi[k] = im[IX(i)];
        }
        pair16<0>(xr, xi, 16, pos);
#pragma unroll
        for (int k = 0; k < 16; k++) {
            int i = g + (k << 4);
            re[IX(i)] = xr[k];
            im[IX(i)] = xi[k];
        }
    }
    __syncthreads();

    /* pair 2: Q=256, elements tid + 256k */
    {
#pragma unroll
        for (int k = 0; k < 16; k++) {
            int i = tid + (k << 8);
            xr[k] = re[IX(i)];
            xi[k] = im[IX(i)];
        }
        pair16<0>(xr, xi, 256, tid);
#pragma unroll
        for (int k = 0; k < 16; k++) {
            int i = tid + (k << 8);
            re[IX(i)] = xr[k];
            im[IX(i)] = xi[k];
        }
    }
    __syncthreads();

    const float sc = 0.5f * 0.015625f;   /* 0.5 (split) * 1/sqrt(4096) */
    for (int k = tid; k <= 2048; k += 256) {
        int k2 = (4096 - k) & 4095;
        float zr  = re[IX(k)],  zi  = im[IX(k)];
        float z2r = re[IX(k2)], z2i = im[IX(k2)];
        float xdr = (zr + z2r) * sc, xdi = (zi - z2i) * sc;
        float xer = (zi + z2i) * sc, xei = (z2r - zr) * sc;
        size_t o = ((size_t)b * Fn + k) * 1024 + d0;
        *(float2*)(g_xfri + o)       = make_float2(xdr, xer);
        *(float2*)(g_xfri + o + 512) = make_float2(xdi, xei);
    }
}

/* ---------------- inverse rfft, two d-columns per block --------------------
   Z = Xd + i*Xe (Hermitian-extended, DC/Nyquist imag zeroed to match numpy);
   out_d = Re(ifft(Z)), out_e = Im(ifft(Z)).                                 */
__global__ __launch_bounds__(256) void fft_inv_kernel() {
    __shared__ float re[4224];
    __shared__ float im[4224];
    int pr = blockIdx.x;
    int b = pr >> 8, d0 = (pr & 255) << 1;
    int tid = threadIdx.x;

    float xr[16], xi[16];

    /* direct digit-reversed Hermitian-extension load into registers */
#pragma unroll
    for (int k = 0; k < 16; k++) {
        unsigned ks = dr4((unsigned)(16 * tid + k));
        float zr, zi;
        if (ks <= 2048) {
            size_t o = ((size_t)b * Fn + ks) * 1024 + d0;
            float2 vre = *(const float2*)(g_of + o);
            float2 vim = *(const float2*)(g_of + o + 512);
            float a = vre.x, c = vre.y, bb = vim.x, dd = vim.y;
            if (ks == 0 || ks == 2048) { bb = 0.f; dd = 0.f; }
            zr = a - dd;
            zi = bb + c;
        } else {
            int k2 = 4096 - (int)ks;
            size_t o = ((size_t)b * Fn + k2) * 1024 + d0;
            float2 vre = *(const float2*)(g_of + o);
            float2 vim = *(const float2*)(g_of + o + 512);
            float a = vre.x, c = vre.y, bb = vim.x, dd = vim.y;
            zr = a + dd;
            zi = c - bb;
        }
        xr[k] = zr;
        xi[k] = zi;
    }
    pair16<1>(xr, xi, 1, 0);
#pragma unroll
    for (int k = 0; k < 16; k++) {
        int i = 16 * tid + k;
        re[IX(i)] = xr[k];
        im[IX(i)] = xi[k];
    }
    __syncthreads();

    /* pair 1: Q=16 */
    {
        int pos = tid & 15, g = ((tid >> 4) << 8) + pos;
#pragma unroll
        for (int k = 0; k < 16; k++) {
            int i = g + (k << 4);
            xr[k] = re[IX(i)];
            xi[k] = im[IX(i)];
        }
        pair16<1>(xr, xi, 16, pos);
#pragma unroll
        for (int k = 0; k < 16; k++) {
            int i = g + (k << 4);
            re[IX(i)] = xr[k];
            im[IX(i)] = xi[k];
        }
    }
    __syncthreads();

    /* pair 2: Q=256; results go straight to global (coalesced across tid) */
    {
#pragma unroll
        for (int k = 0; k < 16; k++) {
            int i = tid + (k << 8);
            xr[k] = re[IX(i)];
            xi[k] = im[IX(i)];
        }
        pair16<1>(xr, xi, 256, tid);
        const float sc = 0.015625f;
#pragma unroll
        for (int k = 0; k < 16; k++) {
            int s = tid + (k << 8);
            *(float2*)(g_ot + ((size_t)b * Sn + s) * Dm + d0) =
                make_float2(xr[k] * sc, xi[k] * sc);
        }
    }
}

/* ==================== pipelined tf32 tensor-core GEMM ====================
   Block tile 128(M) x 64(N) x 32(K), 128 threads = 4 warps (2x2).
   Warp tile 64x32 = 4x4 grid of mma.sync.m16n8k8 tf32 tiles.
   2-stage cp.async pipeline; XOR-swizzled smem (no padding, 48KB).
   MODE 0: g_h   = cvt(g_xfri) @ g_pint + pin_b          (K=1024, N=512)
   MODE 1: g_of  = g_moe  @ g_poutt + pout_b             (K=512,  N=1024)
   MODE 2: g_hid = gelu(gather(g_h) @ g_w1t + b1[e])     (K=512,  N=2048)
   MODE 3: g_eout= g_hid @ g_w2t + b2[e]                 (K=2048, N=512)  */

__device__ __forceinline__ void mma_tf32(float c[4], const unsigned a[4],
                                         const unsigned b[2]) {
    asm volatile(
        "mma.sync.aligned.m16n8k8.row.col.f32.tf32.tf32.f32 "
        "{%0,%1,%2,%3}, {%4,%5,%6,%7}, {%8,%9}, {%0,%1,%2,%3};\n"
        : "+f"(c[0]), "+f"(c[1]), "+f"(c[2]), "+f"(c[3])
        : "r"(a[0]), "r"(a[1]), "r"(a[2]), "r"(a[3]), "r"(b[0]), "r"(b[1]));
}

template <int MODE>
__global__ __launch_bounds__(128) void gemm_tf32_kernel(
        const float* __restrict__ bias) {
    constexpr int K = (MODE == 0) ? 1024 : (MODE == 3) ? 2048 : 512;
    constexpr int N = (MODE == 0) ? 512 : (MODE == 1) ? 1024
                    : (MODE == 2) ? 2048 : 512;
    constexpr int NSTEP = K / 32;

    int e = 0, cnt = NT, base = 0;
    if (MODE >= 2) {
        e = blockIdx.z;
        cnt = g_counts[e];
        base = g_offsets[e];
    }
    int m0 = blockIdx.y * 128;
    if (m0 >= cnt) return;
    int n0 = blockIdx.x * 64;

    const float* Wg = (MODE == 0) ? g_pint : (MODE == 1) ? g_poutt
                    : (MODE == 2) ? g_w1t : g_w2t;
    const float* Wp = Wg + (MODE >= 2 ? (size_t)e * K * N : 0);
    const float* bp = bias + (MODE >= 2 ? (size_t)e * N : 0);

    __shared__ float As[2][128][32];
    __shared__ float Bs[2][32][64];

    int tid = threadIdx.x;
    int wid = tid >> 5, lane = tid & 31;
    int wm = wid >> 1, wn = wid & 1;
    int g = lane >> 2, tq = lane & 3;

    /* A loader: 1024 16B-chunks / 128 thr = 8 each. row=(tid>>3)+16i, chunk=tid&7 */
    int acx = tid & 7;
    int arbase = tid >> 3;
    int ascol = ((acx ^ (arbase & 7)) << 2);
    const float* aptr[8];
#pragma unroll
    for (int i = 0; i < 8; i++) {
        int m = m0 + arbase + i * 16;
        const float* p = nullptr;
        if (m < cnt) {
            if (MODE == 0)      p = g_xfri + (size_t)m * K;
            else if (MODE == 1) p = g_moe + (size_t)m * K;
            else if (MODE == 2) p = g_h + (size_t)g_slot_token[base + m] * K;
            else                p = g_hid + (size_t)(base + m) * K;
        }
        aptr[i] = p;
    }
    /* B loader: 512 chunks / 128 thr = 4 each. row=(tid>>4)+8i, chunk=tid&15 */
    int bcx = tid & 15;
    int brbase = tid >> 4;
    int bscol = ((bcx ^ (brbase & 7)) << 2);

    uint32_t asb[2], bsb[2];
#pragma unroll
    for (int s = 0; s < 2; s++) {
        asb[s] = (uint32_t)__cvta_generic_to_shared(&As[s][0][0]);
        bsb[s] = (uint32_t)__cvta_generic_to_shared(&Bs[s][0][0]);
    }

    auto load_stage = [&](int st, int k0v) {
#pragma unroll
        for (int i = 0; i < 8; i++) {
            int r = arbase + i * 16;
            uint32_t dst = asb[st] + (uint32_t)((r * 32 + ascol) * 4);
            const float* src = aptr[i] ? (aptr[i] + k0v + acx * 4)
                                       : (const float*)g_moe;
            int sz = aptr[i] ? 16 : 0;
            asm volatile("cp.async.cg.shared.global [%0], [%1], 16, %2;"
                         :: "r"(dst), "l"(src), "r"(sz));
        }
#pragma unroll
        for (int i = 0; i < 4; i++) {
            int r = brbase + i * 8;
            uint32_t dst = bsb[st] + (uint32_t)((r * 64 + bscol) * 4);
            const float* src = Wp + (size_t)(k0v + r) * N + n0 + bcx * 4;
            asm volatile("cp.async.cg.shared.global [%0], [%1], 16;"
                         :: "r"(dst), "l"(src));
        }
    };

    float acc[4][4][4];
#pragma unroll
    for (int i = 0; i < 4; i++)
#pragma unroll
        for (int j = 0; j < 4; j++)
#pragma unroll
            for (int r = 0; r < 4; r++) acc[i][j][r] = 0.f;

    load_stage(0, 0);
    asm volatile("cp.async.commit_group;");

    for (int it = 0; it < NSTEP; ++it) {
        int cur = it & 1;
        if (it + 1 < NSTEP) {
            load_stage(cur ^ 1, (it + 1) * 32);
            asm volatile("cp.async.commit_group;");
            asm volatile("cp.async.wait_group 1;");
        } else {
            asm volatile("cp.async.wait_group 0;");
        }
        __syncthreads();

#pragma unroll
        for (int kk = 0; kk < 32; kk += 8) {
            int c0 = kk >> 2;
            unsigned a[4][4];
#pragma unroll
            for (int i = 0; i < 4; i++) {
                int r0 = wm * 64 + i * 16 + g;
                int ca  = ((c0 ^ g) << 2) | tq;
                int ca4 = (((c0 + 1) ^ g) << 2) | tq;
                float v0 = As[cur][r0][ca];
                float v1 = As[cur][r0 + 8][ca];
                float v2 = As[cur][r0][ca4];
                float v3 = As[cur][r0 + 8][ca4];
                if (MODE == 0) {
                    a[i][0] = f2tf(v0); a[i][1] = f2tf(v1);
                    a[i][2] = f2tf(v2); a[i][3] = f2tf(v3);
                } else {
                    a[i][0] = __float_as_uint(v0); a[i][1] = __float_as_uint(v1);
                    a[i][2] = __float_as_uint(v2); a[i][3] = __float_as_uint(v3);
                }
            }
            unsigned b[4][2];
#pragma unroll
            for (int j = 0; j < 4; j++) {
                int cx = wn * 8 + j * 2 + (g >> 2);
                int col0 = ((cx ^ tq) << 2) | (g & 3);
                int col1 = ((cx ^ (4 + tq)) << 2) | (g & 3);
                b[j][0] = __float_as_uint(Bs[cur][kk + tq][col0]);
                b[j][1] = __float_as_uint(Bs[cur][kk + 4 + tq][col1]);
            }
#pragma unroll
            for (int i = 0; i < 4; i++)
#pragma unroll
                for (int j = 0; j < 4; j++) mma_tf32(acc[i][j], a[i], b[j]);
        }
        __syncthreads();
    }

    /* epilogue + writeback */
#pragma unroll
    for (int i = 0; i < 4; i++) {
        int r_lo = m0 + wm * 64 + i * 16 + g;
#pragma unroll
        for (int j = 0; j < 4; j++) {
            int n = n0 + wn * 32 + j * 8 + (tq << 1);
            float bn0 = bp[n], bn1 = bp[n + 1];
#pragma unroll
            for (int h = 0; h < 2; h++) {
                int m = r_lo + h * 8;
                if (m >= cnt) continue;
                float v0 = acc[i][j][h * 2 + 0] + bn0;
                float v1 = acc[i][j][h * 2 + 1] + bn1;
                if (MODE == 0) {
                    /* pre-round h for MoE GEMM1's A path */
                    v0 = __uint_as_float(f2tf(v0));
                    v1 = __uint_as_float(f2tf(v1));
                    *(float2*)(g_h + (size_t)m * N + n) = make_float2(v0, v1);
                } else if (MODE == 2) {
                    v0 = 0.5f * v0 * (1.f + erff(v0 * 0.7071067811865475f));
                    v1 = 0.5f * v1 * (1.f + erff(v1 * 0.7071067811865475f));
                    v0 = __uint_as_float(f2tf(v0));
                    v1 = __uint_as_float(f2tf(v1));
                    *(float2*)(g_hid + (size_t)(base + m) * N + n) =
                        make_float2(v0, v1);
                } else if (MODE == 1) {
                    *(float2*)(g_of + (size_t)m * N + n) = make_float2(v0, v1);
                } else {
                    *(float2*)(g_eout + (size_t)(base + m) * N + n) =
                        make_float2(v0, v1);
                }
            }
        }
    }
}

/* ---------------- fused router: logits from exact g_xfri, top-2, hist ----- */
__global__ __launch_bounds__(256) void logits_topk_kernel() {
    __shared__ float Ws[8][1024];   /* transposed Wr: Ws[e][k], 32KB */
    int tid = threadIdx.x;
    for (int i = tid; i < 8192; i += 256)
        Ws[i & 7][i >> 3] = g_wr[i];
    __syncthreads();

    int wid = tid >> 5, lane = tid & 31;
    int t = blockIdx.x * 8 + wid;
    if (t >= NT) return;

    const float4* xr = (const float4*)(g_xfri + (size_t)t * 1024);
    float acc[8] = {0.f, 0.f, 0.f, 0.f, 0.f, 0.f, 0.f, 0.f};
#pragma unroll
    for (int it = 0; it < 8; ++it) {
        float4 v = xr[it * 32 + lane];
        int k = it * 128 + lane * 4;
#pragma unroll
        for (int e = 0; e < 8; e++) {
            acc[e] += v.x * Ws[e][k]     + v.y * Ws[e][k + 1]
                    + v.z * Ws[e][k + 2] + v.w * Ws[e][k + 3];
        }
    }
#pragma unroll
    for (int e = 0; e < 8; e++)
        for (int o = 16; o; o >>= 1)
            acc[e] += __shfl_down_sync(0xffffffffu, acc[e], o);

    if (lane == 0) {
        float best = -1e30f, second = -1e30f;
        int bi = 0, si = 0;
#pragma unroll
        for (int e = 0; e < 8; e++) {
            float l = acc[e] + g_br[e];
            if (l > best)       { second = best; si = bi; best = l; bi = e; }
            else if (l > second){ second = l; si = e; }
        }
        float e1 = expf(second - best);
        float inv = 1.f / (1.f + e1);
        g_top_idx[2 * t]     = bi;
        g_top_idx[2 * t + 1] = si;
        g_top_w[2 * t]       = inv;
        g_top_w[2 * t + 1]   = e1 * inv;
        atomicAdd(&g_counts[bi], 1);
        atomicAdd(&g_counts[si], 1);
    }
}

__global__ void scan_kernel() {
    if (threadIdx.x == 0) {
        int off = 0;
        for (int e = 0; e < Em; e++) {
            g_offsets[e] = off;
            g_cursor[e]  = off;
            off += g_counts[e];
        }
    }
}

__global__ void scatter_kernel() {
    int t = blockIdx.x * blockDim.x + threadIdx.x;
    if (t < NT) {
        for (int k = 0; k < 2; k++) {
            int e = g_top_idx[2 * t + k];
            int slot = atomicAdd(&g_cursor[e], 1);
            g_slot_token[slot] = t;
            g_tok_slot[2 * t + k] = slot;
        }
    }
}

/* ---------------- combine top-2 expert outputs (deterministic) ------------
   writes tf32-rounded g_moe (pout GEMM A path needs no runtime cvt)        */
__global__ void combine_kernel() {
    int i = blockIdx.x * blockDim.x + threadIdx.x;
    if (i >= NT * Dm) return;
    int t = i >> 9, d = i & 511;
    int s0 = g_tok_slot[2 * t], s1 = g_tok_slot[2 * t + 1];
    float v = g_top_w[2 * t]     * g_eout[(size_t)s0 * Dm + d]
            + g_top_w[2 * t + 1] * g_eout[(size_t)s1 * Dm + d];
    g_moe[i] = __uint_as_float(f2tf(v));
}

/* ---------------- LayerNorm + residual ---------------- */
__global__ void ln_kernel(const float* __restrict__ x,
                          const float* __restrict__ gg,
                          const float* __restrict__ bb,
                          float* __restrict__ out) {
    int row = blockIdx.x;              /* 0 .. B*S-1 */
    int tid = threadIdx.x;             /* 128 threads */
    const float* v = g_ot + (size_t)row * Dm;

    float loc[4];
    float s = 0.f;
#pragma unroll
    for (int i = 0; i < 4; i++) {
        loc[i] = v[tid + i * 128];
        s += loc[i];
    }

    __shared__ float red[4];
    for (int o = 16; o; o >>= 1) s += __shfl_down_sync(0xffffffffu, s, o);
    if ((tid & 31) == 0) red[tid >> 5] = s;
    __syncthreads();
    float mu = (red[0] + red[1] + red[2] + red[3]) * (1.f / 512.f);
    __syncthreads();

    float q = 0.f;
#pragma unroll
    for (int i = 0; i < 4; i++) {
        float dd = loc[i] - mu;
        q += dd * dd;
    }
    for (int o = 16; o; o >>= 1) q += __shfl_down_sync(0xffffffffu, q, o);
    if ((tid & 31) == 0) red[tid >> 5] = q;
    __syncthreads();
    float var = (red[0] + red[1] + red[2] + red[3]) * (1.f / 512.f);
    float rs = rsqrtf(var + 1e-5f);

#pragma unroll
    for (int i = 0; i < 4; i++) {
        int d = tid + i * 128;
        size_t o = (size_t)row * Dm + d;
        out[o] = (loc[i] - mu) * rs * gg[d] + bb[d] + x[o];
    }
}

/* ---------------- launch ---------------- */
extern "C" void kernel_launch(void* const* d_in, const int* in_sizes, int n_in,
                              void* d_out, int out_size) {
    const float* x        = (const float*)d_in[0];
    const float* pin_w    = (const float*)d_in[1];
    const float* pin_b    = (const float*)d_in[2];
    const float* router_w = (const float*)d_in[3];
    const float* router_b = (const float*)d_in[4];
    const float* w1       = (const float*)d_in[5];
    const float* b1       = (const float*)d_in[6];
    const float* w2       = (const float*)d_in[7];
    const float* b2       = (const float*)d_in[8];
    const float* pout_w   = (const float*)d_in[9];
    const float* pout_b   = (const float*)d_in[10];
    const float* ln_g     = (const float*)d_in[11];
    const float* ln_b     = (const float*)d_in[12];
    float* out = (float*)d_out;

    const int MB = (NT + 127) / 128;   /* 129 M-tiles for tf32 kernels */

    setup_kernel<<<16, 256>>>();
    preround_kernel<<<32768, 256>>>(w1, w2, pout_w, pin_w);
    wr_kernel<<<1025, 128>>>(pin_w, pin_b, router_w, router_b);
    fft_fwd_kernel<<<Bn * 256, 256>>>(x);
    gemm_tf32_kernel<0><<<dim3(512 / 64, MB), 128>>>(pin_b);
    logits_topk_kernel<<<(NT + 7) / 8, 256>>>();
    scan_kernel<<<1, 1>>>();
    scatter_kernel<<<(NT + 255) / 256, 256>>>();
    gemm_tf32_kernel<2><<<dim3(DFF / 64, MB, Em), 128>>>(b1);
    gemm_tf32_kernel<3><<<dim3(Dm / 64, MB, Em), 128>>>(b2);
    combine_kernel<<<(NT * Dm + 255) / 256, 256>>>();
    gemm_tf32_kernel<1><<<dim3(1024 / 64, MB), 128>>>(pout_b);
    fft_inv_kernel<<<Bn * 256, 256>>>();
    ln_kernel<<<Bn * Sn, 128>>>(x, ln_g, ln_b, out);
}

// round 11
// speedup vs baseline: 4.0908x; 1.0217x over previous
#include <cuda_runtime.h>
#include <cstdint>

#define Bn   8
#define Sn   4096
#define Dm   512
#define Fn   2049
#define Em   8
#define DFF  2048
#define NT   (Bn * Fn)      /* 16392 tokens in frequency domain */
#define NSLOT (2 * NT)      /* 32784 token-expert slots */

/* ---------------- scratch (device globals; no runtime alloc allowed) -------- */
__device__ float g_xfri[16785408];   /* NT x 1024  (re | im), EXACT fp32 */
__device__ float g_h   [8392704];    /* NT x 512  (tf32-rounded at pin epi) */
__device__ float g_moe [8392704];    /* NT x 512  (tf32-rounded at combine) */
__device__ float g_of  [16785408];   /* NT x 1024 */
__device__ float g_ot  [16777216];   /* B x S x D */
__device__ float g_hid [67141632];   /* NSLOT x 2048 (tf32-rounded at store) */
__device__ float g_eout[16785408];   /* NSLOT x 512 */
__device__ float g_w1t [8388608];    /* tf32-rounded w1 */
__device__ float g_w2t [8388608];    /* tf32-rounded w2 */
__device__ float g_poutt[524288];    /* tf32-rounded pout_w */
__device__ float g_pint [524288];    /* tf32-rounded pin_w */
__device__ float g_wr  [8192];       /* fused router weights pin_w @ router_w */
__device__ float g_br  [8];          /* fused router bias */
__device__ float2 g_tw [4096];       /* twiddle table: index = half + pos */
__device__ int   g_top_idx[NT * 2];
__device__ float g_top_w [NT * 2];
__device__ int   g_counts[Em];
__device__ int   g_offsets[Em];
__device__ int   g_cursor[Em];
__device__ int   g_slot_token[NSLOT];
__device__ int   g_tok_slot[NT * 2];

__device__ __forceinline__ unsigned f2tf(float f) {
    unsigned u;
    asm("cvt.rna.tf32.f32 %0, %1;" : "=r"(u) : "f"(f));
    return u;
}

/* ---------------- setup: zero counts + build twiddle table ---------------- */
__global__ void setup_kernel() {
    int i = blockIdx.x * blockDim.x + threadIdx.x;
    if (i < Em) g_counts[i] = 0;
    if (i >= 1 && i < 4096) {
        int half = 1 << (31 - __clz(i));
        int pos  = i - half;
        float ang = -6.283185307179586f * (float)pos / (float)(2 * half);
        float sn, cs;
        sincosf(ang, &sn, &cs);
        g_tw[i] = make_float2(cs, sn);
    }
}

/* ---------------- pre-round weights to tf32 (once per launch) ------------- */
__global__ void preround_kernel(const float* __restrict__ w1,
                                const float* __restrict__ w2,
                                const float* __restrict__ pw,
                                const float* __restrict__ piw) {
    int i = blockIdx.x * blockDim.x + threadIdx.x;
    if (i < 8388608) {
        g_w1t[i] = __uint_as_float(f2tf(w1[i]));
        g_w2t[i] = __uint_as_float(f2tf(w2[i]));
    }
    if (i < 524288) {
        g_poutt[i] = __uint_as_float(f2tf(pw[i]));
        g_pint[i]  = __uint_as_float(f2tf(piw[i]));
    }
}

/* ---------------- fused router weights: Wr = pin_w @ router_w ------------- */
__global__ void wr_kernel(const float* __restrict__ pin_w,
                          const float* __restrict__ pin_b,
                          const float* __restrict__ rw,
                          const float* __restrict__ rb) {
    int f = blockIdx.x, tid = threadIdx.x;
    if (f == 1024) {
        if (tid < 8) {
            float s = rb[tid];
            for (int d = 0; d < 512; d++) s += pin_b[d] * rw[d * 8 + tid];
            g_br[tid] = s;
        }
        return;
    }
    float acc[8] = {0.f, 0.f, 0.f, 0.f, 0.f, 0.f, 0.f, 0.f};
    for (int d = tid; d < 512; d += 128) {
        float pv = pin_w[f * 512 + d];
        const float* r = rw + d * 8;
#pragma unroll
        for (int e = 0; e < 8; e++) acc[e] += pv * r[e];
    }
    __shared__ float red[4][8];
#pragma unroll
    for (int e = 0; e < 8; e++)
        for (int o = 16; o; o >>= 1)
            acc[e] += __shfl_down_sync(0xffffffffu, acc[e], o);
    if ((tid & 31) == 0) {
#pragma unroll
        for (int e = 0; e < 8; e++) red[tid >> 5][e] = acc[e];
    }
    __syncthreads();
    if (tid < 8)
        g_wr[f * 8 + tid] = red[0][tid] + red[1][tid] + red[2][tid] + red[3][tid];
}

/* skewed smem index: kills 2-way bank conflicts in butterfly stages */
#define IX(i) ((i) + ((i) >> 5))

/* base-4 digit reversal of a 12-bit index: bitrev then swap adjacent bits */
__device__ __forceinline__ unsigned dr4(unsigned s) {
    unsigned t = __brev(s) >> 20;
    return ((t & 0x555u) << 1) | ((t >> 1) & 0x555u);
}

/* one radix-4 DIT butterfly on register elements 0, S, 2S, 3S */
template <int INV, int S>
__device__ __forceinline__ void bfly4(float* xr, float* xi,
                                      float2 w1, float2 w2) {
    float w1i = INV ? -w1.y : w1.y;
    float w2i = INV ? -w2.y : w2.y;
    float w3r = w1.x * w2.x - w1i * w2i;
    float w3i = w1.x * w2i + w1i * w2.x;
    float t0r = xr[0], t0i = xi[0];
    float t1r = xr[S] * w1.x - xi[S] * w1i;
    float t1i = xr[S] * w1i + xi[S] * w1.x;
    float t2r = xr[2 * S] * w2.x - xi[2 * S] * w2i;
    float t2i = xr[2 * S] * w2i + xi[2 * S] * w2.x;
    float t3r = xr[3 * S] * w3r - xi[3 * S] * w3i;
    float t3i = xr[3 * S] * w3i + xi[3 * S] * w3r;
    float s0r = t0r + t2r, s0i = t0i + t2i;
    float s1r = t0r - t2r, s1i = t0i - t2i;
    float s2r = t1r + t3r, s2i = t1i + t3i;
    float s3r = t1r - t3r, s3i = t1i - t3i;
    xr[0] = s0r + s2r;     xi[0] = s0i + s2i;
    xr[2 * S] = s0r - s2r; xi[2 * S] = s0i - s2i;
    if (!INV) {
        xr[S] = s1r + s3i;     xi[S] = s1i - s3r;     /* s1 - i s3 */
        xr[3 * S] = s1r - s3i; xi[3 * S] = s1i + s3r; /* s1 + i s3 */
    } else {
        xr[S] = s1r - s3i;     xi[S] = s1i + s3r;
        xr[3 * S] = s1r + s3i; xi[3 * S] = s1i - s3r;
    }
}

/* fused pair of radix-4 stages on a 16-register group.
   Registers hold elements g + k*Q (k=0..15), pos = g mod Q. */
template <int INV>
__device__ __forceinline__ void pair16(float* xr, float* xi, int Q, int pos) {
    float2 wA1 = g_tw[2 * Q + pos];
    float2 wA2 = g_tw[Q + pos];
#pragma unroll
    for (int b = 0; b < 4; b++)
        bfly4<INV, 1>(xr + 4 * b, xi + 4 * b, wA1, wA2);
#pragma unroll
    for (int c = 0; c < 4; c++) {
        float2 wB1 = g_tw[8 * Q + pos + c * Q];
        float2 wB2 = g_tw[4 * Q + pos + c * Q];
        bfly4<INV, 4>(xr + c, xi + c, wB1, wB2);
    }
}

/* ---------------- forward rfft, two d-columns per block (two-for-one) ------ */
__global__ __launch_bounds__(256) void fft_fwd_kernel(const float* __restrict__ x) {
    __shared__ float re[4224];
    __shared__ float im[4224];
    int pr = blockIdx.x;
    int b = pr >> 8, d0 = (pr & 255) << 1;
    int tid = threadIdx.x;

    float xr[16], xi[16];

#pragma unroll
    for (int k = 0; k < 16; k++) {
        unsigned s = dr4((unsigned)(16 * tid + k));
        float2 v = *(const float2*)(x + ((size_t)b * Sn + s) * Dm + d0);
        xr[k] = v.x;
        xi[k] = v.y;
    }
    pair16<0>(xr, xi, 1, 0);
#pragma unroll
    for (int k = 0; k < 16; k++) {
        int i = 16 * tid + k;
        re[IX(i)] = xr[k];
        im[IX(i)] = xi[k];
    }
    __syncthreads();

    {
        int pos = tid & 15, g = ((tid >> 4) << 8) + pos;
#pragma unroll
        for (int k = 0; k < 16; k++) {
            int i = g + (k << 4);
            xr[k] = re[IX(i)];
            xi[k] = im[IX(i)];
        }
        pair16<0>(xr, xi, 16, pos);
#pragma unroll
        for (int k = 0; k < 16; k++) {
            int i = g + (k << 4);
            re[IX(i)] = xr[k];
            im[IX(i)] = xi[k];
        }
    }
    __syncthreads();

    {
#pragma unroll
        for (int k = 0; k < 16; k++) {
            int i = tid + (k << 8);
            xr[k] = re[IX(i)];
            xi[k] = im[IX(i)];
        }
        pair16<0>(xr, xi, 256, tid);
#pragma unroll
        for (int k = 0; k < 16; k++) {
            int i = tid + (k << 8);
            re[IX(i)] = xr[k];
            im[IX(i)] = xi[k];
        }
    }
    __syncthreads();

    const float sc = 0.5f * 0.015625f;   /* 0.5 (split) * 1/sqrt(4096) */
    for (int k = tid; k <= 2048; k += 256) {
        int k2 = (4096 - k) & 4095;
        float zr  = re[IX(k)],  zi  = im[IX(k)];
        float z2r = re[IX(k2)], z2i = im[IX(k2)];
        float xdr = (zr + z2r) * sc, xdi = (zi - z2i) * sc;
        float xer = (zi + z2i) * sc, xei = (z2r - zr) * sc;
        size_t o = ((size_t)b * Fn + k) * 1024 + d0;
        *(float2*)(g_xfri + o)       = make_float2(xdr, xer);
        *(float2*)(g_xfri + o + 512) = make_float2(xdi, xei);
    }
}

/* ---------------- inverse rfft, two d-columns per block -------------------- */
__global__ __launch_bounds__(256) void fft_inv_kernel() {
    __shared__ float re[4224];
    __shared__ float im[4224];
    int pr = blockIdx.x;
    int b = pr >> 8, d0 = (pr & 255) << 1;
    int tid = threadIdx.x;

    float xr[16], xi[16];

#pragma unroll
    for (int k = 0; k < 16; k++) {
        unsigned ks = dr4((unsigned)(16 * tid + k));
        float zr, zi;
        if (ks <= 2048) {
            size_t o = ((size_t)b * Fn + ks) * 1024 + d0;
            float2 vre = *(const float2*)(g_of + o);
            float2 vim = *(const float2*)(g_of + o + 512);
            float a = vre.x, c = vre.y, bb = vim.x, dd = vim.y;
            if (ks == 0 || ks == 2048) { bb = 0.f; dd = 0.f; }
            zr = a - dd;
            zi = bb + c;
        } else {
            int k2 = 4096 - (int)ks;
            size_t o = ((size_t)b * Fn + k2) * 1024 + d0;
            float2 vre = *(const float2*)(g_of + o);
            float2 vim = *(const float2*)(g_of + o + 512);
            float a = vre.x, c = vre.y, bb = vim.x, dd = vim.y;
            zr = a + dd;
            zi = c - bb;
        }
        xr[k] = zr;
        xi[k] = zi;
    }
    pair16<1>(xr, xi, 1, 0);
#pragma unroll
    for (int k = 0; k < 16; k++) {
        int i = 16 * tid + k;
        re[IX(i)] = xr[k];
        im[IX(i)] = xi[k];
    }
    __syncthreads();

    {
        int pos = tid & 15, g = ((tid >> 4) << 8) + pos;
#pragma unroll
        for (int k = 0; k < 16; k++) {
            int i = g + (k << 4);
            xr[k] = re[IX(i)];
            xi[k] = im[IX(i)];
        }
        pair16<1>(xr, xi, 16, pos);
#pragma unroll
        for (int k = 0; k < 16; k++) {
            int i = g + (k << 4);
            re[IX(i)] = xr[k];
            im[IX(i)] = xi[k];
        }
    }
    __syncthreads();

    {
#pragma unroll
        for (int k = 0; k < 16; k++) {
            int i = tid + (k << 8);
            xr[k] = re[IX(i)];
            xi[k] = im[IX(i)];
        }
        pair16<1>(xr, xi, 256, tid);
        const float sc = 0.015625f;
#pragma unroll
        for (int k = 0; k < 16; k++) {
            int s = tid + (k << 8);
            *(float2*)(g_ot + ((size_t)b * Sn + s) * Dm + d0) =
                make_float2(xr[k] * sc, xi[k] * sc);
        }
    }
}

/* ==================== pipelined tf32 tensor-core GEMM ====================
   Block tile 128(M) x 128(N) x 32(K), 256 threads = 8 warps (2x4).
   Warp tile 64x32 = 4x4 grid of mma.sync.m16n8k8 tf32 tiles.
   2-stage cp.async pipeline; XOR-swizzled dynamic smem (64KB).
   MODE 0: g_h   = cvt(g_xfri) @ g_pint + pin_b          (K=1024, N=512)
   MODE 1: g_of  = g_moe  @ g_poutt + pout_b             (K=512,  N=1024)
   MODE 2: g_hid = gelu(gather(g_h) @ g_w1t + b1[e])     (K=512,  N=2048)
   MODE 3: g_eout= g_hid @ g_w2t + b2[e]                 (K=2048, N=512)  */

__device__ __forceinline__ void mma_tf32(float c[4], const unsigned a[4],
                                         const unsigned b[2]) {
    asm volatile(
        "mma.sync.aligned.m16n8k8.row.col.f32.tf32.tf32.f32 "
        "{%0,%1,%2,%3}, {%4,%5,%6,%7}, {%8,%9}, {%0,%1,%2,%3};\n"
        : "+f"(c[0]), "+f"(c[1]), "+f"(c[2]), "+f"(c[3])
        : "r"(a[0]), "r"(a[1]), "r"(a[2]), "r"(a[3]), "r"(b[0]), "r"(b[1]));
}

/* dynamic smem layout (floats):
   As[2][128][32] at 0 (stage s at s*4096)
   Bs[2][32][128] at 8192 (stage s at 8192 + s*4096)                       */
template <int MODE>
__global__ __launch_bounds__(256) void gemm_tf32_kernel(
        const float* __restrict__ bias) {
    constexpr int K = (MODE == 0) ? 1024 : (MODE == 3) ? 2048 : 512;
    constexpr int N = (MODE == 0) ? 512 : (MODE == 1) ? 1024
                    : (MODE == 2) ? 2048 : 512;
    constexpr int NSTEP = K / 32;

    extern __shared__ float smem[];
    float* AsBase = smem;          /* 2 * 4096 floats */
    float* BsBase = smem + 8192;   /* 2 * 4096 floats */

    int e = 0, cnt = NT, base = 0;
    if (MODE >= 2) {
        e = blockIdx.z;
        cnt = g_counts[e];
        base = g_offsets[e];
    }
    int m0 = blockIdx.y * 128;
    if (m0 >= cnt) return;
    int n0 = blockIdx.x * 128;

    const float* Wg = (MODE == 0) ? g_pint : (MODE == 1) ? g_poutt
                    : (MODE == 2) ? g_w1t : g_w2t;
    const float* Wp = Wg + (MODE >= 2 ? (size_t)e * K * N : 0);
    const float* bp = bias + (MODE >= 2 ? (size_t)e * N : 0);

    int tid = threadIdx.x;
    int wid = tid >> 5, lane = tid & 31;
    int wm = wid >> 2, wn = wid & 3;
    int g = lane >> 2, tq = lane & 3;

    /* A loader: 1024 16B-chunks / 256 thr = 4 each. row=(tid>>3)+32i, chunk=tid&7 */
    int acx = tid & 7;
    int arbase = tid >> 3;                       /* 0..31 */
    int ascol = ((acx ^ (arbase & 7)) << 2);
    const float* aptr[4];
#pragma unroll
    for (int i = 0; i < 4; i++) {
        int m = m0 + arbase + i * 32;
        const float* p = nullptr;
        if (m < cnt) {
            if (MODE == 0)      p = g_xfri + (size_t)m * K;
            else if (MODE == 1) p = g_moe + (size_t)m * K;
            else if (MODE == 2) p = g_h + (size_t)g_slot_token[base + m] * K;
            else                p = g_hid + (size_t)(base + m) * K;
        }
        aptr[i] = p;
    }
    /* B loader: 32 rows x 32 chunks = 1024 chunks / 256 thr = 4 each.
       row=(tid>>5)+8i, chunk=tid&31 */
    int bcx = tid & 31;
    int brbase = tid >> 5;                       /* 0..7 */
    int bscol = ((bcx ^ brbase) << 2);           /* brbase = row&7 for all i */

    uint32_t asb[2], bsb[2];
#pragma unroll
    for (int s = 0; s < 2; s++) {
        asb[s] = (uint32_t)__cvta_generic_to_shared(AsBase + s * 4096);
        bsb[s] = (uint32_t)__cvta_generic_to_shared(BsBase + s * 4096);
    }

    auto load_stage = [&](int st, int k0v) {
#pragma unroll
        for (int i = 0; i < 4; i++) {
            int r = arbase + i * 32;
            uint32_t dst = asb[st] + (uint32_t)((r * 32 + ascol) * 4);
            const float* src = aptr[i] ? (aptr[i] + k0v + acx * 4)
                                       : (const float*)g_moe;
            int sz = aptr[i] ? 16 : 0;
            asm volatile("cp.async.cg.shared.global [%0], [%1], 16, %2;"
                         :: "r"(dst), "l"(src), "r"(sz));
        }
#pragma unroll
        for (int i = 0; i < 4; i++) {
            int r = brbase + i * 8;
            uint32_t dst = bsb[st] + (uint32_t)((r * 128 + bscol) * 4);
            const float* src = Wp + (size_t)(k0v + r) * N + n0 + bcx * 4;
            asm volatile("cp.async.cg.shared.global [%0], [%1], 16;"
                         :: "r"(dst), "l"(src));
        }
    };

    float acc[4][4][4];
#pragma unroll
    for (int i = 0; i < 4; i++)
#pragma unroll
        for (int j = 0; j < 4; j++)
#pragma unroll
            for (int r = 0; r < 4; r++) acc[i][j][r] = 0.f;

    load_stage(0, 0);
    asm volatile("cp.async.commit_group;");

    for (int it = 0; it < NSTEP; ++it) {
        int cur = it & 1;
        if (it + 1 < NSTEP) {
            load_stage(cur ^ 1, (it + 1) * 32);
            asm volatile("cp.async.commit_group;");
            asm volatile("cp.async.wait_group 1;");
        } else {
            asm volatile("cp.async.wait_group 0;");
        }
        __syncthreads();

        float* Asc = AsBase + cur * 4096;
        float* Bsc = BsBase + cur * 4096;

#pragma unroll
        for (int kk = 0; kk < 32; kk += 8) {
            int c0 = kk >> 2;
            unsigned a[4][4];
#pragma unroll
            for (int i = 0; i < 4; i++) {
                int r0 = wm * 64 + i * 16 + g;
                int ca  = ((c0 ^ g) << 2) | tq;
                int ca4 = (((c0 + 1) ^ g) << 2) | tq;
                float v0 = Asc[r0 * 32 + ca];
                float v1 = Asc[(r0 + 8) * 32 + ca];
                float v2 = Asc[r0 * 32 + ca4];
                float v3 = Asc[(r0 + 8) * 32 + ca4];
                if (MODE == 0) {
                    a[i][0] = f2tf(v0); a[i][1] = f2tf(v1);
                    a[i][2] = f2tf(v2); a[i][3] = f2tf(v3);
                } else {
                    a[i][0] = __float_as_uint(v0); a[i][1] = __float_as_uint(v1);
                    a[i][2] = __float_as_uint(v2); a[i][3] = __float_as_uint(v3);
                }
            }
            unsigned b[4][2];
#pragma unroll
            for (int j = 0; j < 4; j++) {
                int cx = wn * 8 + j * 2 + (g >> 2);          /* 0..31 */
                int col0 = ((cx ^ tq) << 2) | (g & 3);
                int col1 = ((cx ^ (4 + tq)) << 2) | (g & 3);
                b[j][0] = __float_as_uint(Bsc[(kk + tq) * 128 + col0]);
                b[j][1] = __float_as_uint(Bsc[(kk + 4 + tq) * 128 + col1]);
            }
#pragma unroll
            for (int i = 0; i < 4; i++)
#pragma unroll
                for (int j = 0; j < 4; j++) mma_tf32(acc[i][j], a[i], b[j]);
        }
        __syncthreads();
    }

    /* epilogue + writeback */
#pragma unroll
    for (int i = 0; i < 4; i++) {
        int r_lo = m0 + wm * 64 + i * 16 + g;
#pragma unroll
        for (int j = 0; j < 4; j++) {
            int n = n0 + wn * 32 + j * 8 + (tq << 1);
            float bn0 = bp[n], bn1 = bp[n + 1];
#pragma unroll
            for (int h = 0; h < 2; h++) {
                int m = r_lo + h * 8;
                if (m >= cnt) continue;
                float v0 = acc[i][j][h * 2 + 0] + bn0;
                float v1 = acc[i][j][h * 2 + 1] + bn1;
                if (MODE == 0) {
                    v0 = __uint_as_float(f2tf(v0));
                    v1 = __uint_as_float(f2tf(v1));
                    *(float2*)(g_h + (size_t)m * N + n) = make_float2(v0, v1);
                } else if (MODE == 2) {
                    v0 = 0.5f * v0 * (1.f + erff(v0 * 0.7071067811865475f));
                    v1 = 0.5f * v1 * (1.f + erff(v1 * 0.7071067811865475f));
                    v0 = __uint_as_float(f2tf(v0));
                    v1 = __uint_as_float(f2tf(v1));
                    *(float2*)(g_hid + (size_t)(base + m) * N + n) =
                        make_float2(v0, v1);
                } else if (MODE == 1) {
                    *(float2*)(g_of + (size_t)m * N + n) = make_float2(v0, v1);
                } else {
                    *(float2*)(g_eout + (size_t)(base + m) * N + n) =
                        make_float2(v0, v1);
                }
            }
        }
    }
}

/* ---------------- fused router: logits from exact g_xfri, top-2, hist ----- */
__global__ __launch_bounds__(256) void logits_topk_kernel() {
    __shared__ float Ws[8][1024];   /* transposed Wr: Ws[e][k], 32KB */
    int tid = threadIdx.x;
    for (int i = tid; i < 8192; i += 256)
        Ws[i & 7][i >> 3] = g_wr[i];
    __syncthreads();

    int wid = tid >> 5, lane = tid & 31;
    int t = blockIdx.x * 8 + wid;
    if (t >= NT) return;

    const float4* xr = (const float4*)(g_xfri + (size_t)t * 1024);
    float acc[8] = {0.f, 0.f, 0.f, 0.f, 0.f, 0.f, 0.f, 0.f};
#pragma unroll
    for (int it = 0; it < 8; ++it) {
        float4 v = xr[it * 32 + lane];
        int k = it * 128 + lane * 4;
#pragma unroll
        for (int e = 0; e < 8; e++) {
            acc[e] += v.x * Ws[e][k]     + v.y * Ws[e][k + 1]
                    + v.z * Ws[e][k + 2] + v.w * Ws[e][k + 3];
        }
    }
#pragma unroll
    for (int e = 0; e < 8; e++)
        for (int o = 16; o; o >>= 1)
            acc[e] += __shfl_down_sync(0xffffffffu, acc[e], o);

    if (lane == 0) {
        float best = -1e30f, second = -1e30f;
        int bi = 0, si = 0;
#pragma unroll
        for (int e = 0; e < 8; e++) {
            float l = acc[e] + g_br[e];
            if (l > best)       { second = best; si = bi; best = l; bi = e; }
            else if (l > second){ second = l; si = e; }
        }
        float e1 = expf(second - best);
        float inv = 1.f / (1.f + e1);
        g_top_idx[2 * t]     = bi;
        g_top_idx[2 * t + 1] = si;
        g_top_w[2 * t]       = inv;
        g_top_w[2 * t + 1]   = e1 * inv;
        atomicAdd(&g_counts[bi], 1);
        atomicAdd(&g_counts[si], 1);
    }
}

__global__ void scan_kernel() {
    if (threadIdx.x == 0) {
        int off = 0;
        for (int e = 0; e < Em; e++) {
            g_offsets[e] = off;
            g_cursor[e]  = off;
            off += g_counts[e];
        }
    }
}

__global__ void scatter_kernel() {
    int t = blockIdx.x * blockDim.x + threadIdx.x;
    if (t < NT) {
        for (int k = 0; k < 2; k++) {
            int e = g_top_idx[2 * t + k];
            int slot = atomicAdd(&g_cursor[e], 1);
            g_slot_token[slot] = t;
            g_tok_slot[2 * t + k] = slot;
        }
    }
}

/* ---------------- combine top-2 expert outputs (deterministic) ------------ */
__global__ void combine_kernel() {
    int i = blockIdx.x * blockDim.x + threadIdx.x;
    if (i >= NT * Dm) return;
    int t = i >> 9, d = i & 511;
    int s0 = g_tok_slot[2 * t], s1 = g_tok_slot[2 * t + 1];
    float v = g_top_w[2 * t]     * g_eout[(size_t)s0 * Dm + d]
            + g_top_w[2 * t + 1] * g_eout[(size_t)s1 * Dm + d];
    g_moe[i] = __uint_as_float(f2tf(v));
}

/* ---------------- LayerNorm + residual ---------------- */
__global__ void ln_kernel(const float* __restrict__ x,
                          const float* __restrict__ gg,
                          const float* __restrict__ bb,
                          float* __restrict__ out) {
    int row = blockIdx.x;              /* 0 .. B*S-1 */
    int tid = threadIdx.x;             /* 128 threads */
    const float* v = g_ot + (size_t)row * Dm;

    float loc[4];
    float s = 0.f;
#pragma unroll
    for (int i = 0; i < 4; i++) {
        loc[i] = v[tid + i * 128];
        s += loc[i];
    }

    __shared__ float red[4];
    for (int o = 16; o; o >>= 1) s += __shfl_down_sync(0xffffffffu, s, o);
    if ((tid & 31) == 0) red[tid >> 5] = s;
    __syncthreads();
    float mu = (red[0] + red[1] + red[2] + red[3]) * (1.f / 512.f);
    __syncthreads();

    float q = 0.f;
#pragma unroll
    for (int i = 0; i < 4; i++) {
        float dd = loc[i] - mu;
        q += dd * dd;
    }
    for (int o = 16; o; o >>= 1) q += __shfl_down_sync(0xffffffffu, q, o);
    if ((tid & 31) == 0) red[tid >> 5] = q;
    __syncthreads();
    float var = (red[0] + red[1] + red[2] + red[3]) * (1.f / 512.f);
    float rs = rsqrtf(var + 1e-5f);

#pragma unroll
    for (int i = 0; i < 4; i++) {
        int d = tid + i * 128;
        size_t o = (size_t)row * Dm + d;
        out[o] = (loc[i] - mu) * rs * gg[d] + bb[d] + x[o];
    }
}

/* ---------------- launch ---------------- */
extern "C" void kernel_launch(void* const* d_in, const int* in_sizes, int n_in,
                              void* d_out, int out_size) {
    const float* x        = (const float*)d_in[0];
    const float* pin_w    = (const float*)d_in[1];
    const float* pin_b    = (const float*)d_in[2];
    const float* router_w = (const float*)d_in[3];
    const float* router_b = (const float*)d_in[4];
    const float* w1       = (const float*)d_in[5];
    const float* b1       = (const float*)d_in[6];
    const float* w2       = (const float*)d_in[7];
    const float* b2       = (const float*)d_in[8];
    const float* pout_w   = (const float*)d_in[9];
    const float* pout_b   = (const float*)d_in[10];
    const float* ln_g     = (const float*)d_in[11];
    const float* ln_b     = (const float*)d_in[12];
    float* out = (float*)d_out;

    const int MB = (NT + 127) / 128;   /* 129 M-tiles for tf32 kernels */
    const int GSM = 65536;             /* 64KB dynamic smem for GEMM */

    /* opt-in >48KB dynamic smem (idempotent; runs outside stream ops) */
    cudaFuncSetAttribute(gemm_tf32_kernel<0>,
                         cudaFuncAttributeMaxDynamicSharedMemorySize, GSM);
    cudaFuncSetAttribute(gemm_tf32_kernel<1>,
                         cudaFuncAttributeMaxDynamicSharedMemorySize, GSM);
    cudaFuncSetAttribute(gemm_tf32_kernel<2>,
                         cudaFuncAttributeMaxDynamicSharedMemorySize, GSM);
    cudaFuncSetAttribute(gemm_tf32_kernel<3>,
                         cudaFuncAttributeMaxDynamicSharedMemorySize, GSM);

    setup_kernel<<<16, 256>>>();
    preround_kernel<<<32768, 256>>>(w1, w2, pout_w, pin_w);
    wr_kernel<<<1025, 128>>>(pin_w, pin_b, router_w, router_b);
    fft_fwd_kernel<<<Bn * 256, 256>>>(x);
    gemm_tf32_kernel<0><<<dim3(512 / 128, MB), 256, GSM>>>(pin_b);
    logits_topk_kernel<<<(NT + 7) / 8, 256>>>();
    scan_kernel<<<1, 1>>>();
    scatter_kernel<<<(NT + 255) / 256, 256>>>();
    gemm_tf32_kernel<2><<<dim3(DFF / 128, MB, Em), 256, GSM>>>(b1);
    gemm_tf32_kernel<3><<<dim3(Dm / 128, MB, Em), 256, GSM>>>(b2);
    combine_kernel<<<(NT * Dm + 255) / 256, 256>>>();
    gemm_tf32_kernel<1><<<dim3(1024 / 128, MB), 256, GSM>>>(pout_b);
    fft_inv_kernel<<<Bn * 256, 256>>>();
    ln_kernel<<<Bn * Sn, 128>>>(x, ln_g, ln_b, out);
}